// round 2
// baseline (speedup 1.0000x reference)
#include <cuda_runtime.h>
#include <math.h>

#define BB 2
#define SS 2048
#define DD 1024
#define NHH 16
#define HDD 64
#define FFF 4096
#define RR (BB*SS)   // 4096 rows

// ---------------- scratch (no allocs allowed; __device__ globals) ----------------
// Reuse plan: g_h holds LN1 out, later reused for LN2 out.
//             g_q holds Q, later reused for x2 (= x + o-proj).
__device__ float g_h [RR*DD];                       // LN1 out  / LN2 out
__device__ float g_q [RR*DD];                       // Q        / x2
__device__ float g_kv[RR*2*DD];                     // K|V (b,s,(h,d) | D + (h,d))
__device__ float g_ao[RR*DD];                       // attn output (b,s,(h,d))
__device__ float g_ff[(size_t)RR*FFF];              // FFN hidden
__device__ float g_P [(size_t)BB*NHH*SS*SS];        // softmax probs (b,h,n,m)

// ---------------- LayerNorm: one block per row, 256 thr, 4 elems/thr -------------
__global__ void __launch_bounds__(256)
ln_kernel(const float* __restrict__ x, const float* __restrict__ g,
          const float* __restrict__ beta, float* __restrict__ out)
{
    __shared__ float red[64];
    int row = blockIdx.x;
    const float* xr = x + (size_t)row*DD;
    float* orow = out + (size_t)row*DD;
    int t = threadIdx.x;
    float v[4]; float s = 0.f, sq = 0.f;
#pragma unroll
    for (int i = 0; i < 4; i++) {
        v[i] = xr[t + i*256];
        s += v[i];
        sq = fmaf(v[i], v[i], sq);
    }
#pragma unroll
    for (int o = 16; o > 0; o >>= 1) {
        s  += __shfl_down_sync(0xffffffffu, s,  o);
        sq += __shfl_down_sync(0xffffffffu, sq, o);
    }
    int lane = t & 31, w = t >> 5;
    if (lane == 0) { red[w] = s; red[w + 32] = sq; }
    __syncthreads();
    if (t == 0) {
        float ts = 0.f, tq = 0.f;
        for (int i = 0; i < 8; i++) { ts += red[i]; tq += red[i + 32]; }
        float mu  = ts * (1.0f / DD);
        float var = tq * (1.0f / DD) - mu * mu;
        red[0] = mu;
        red[1] = rsqrtf(var + 1e-5f);
    }
    __syncthreads();
    float mu = red[0], r = red[1];
#pragma unroll
    for (int i = 0; i < 4; i++) {
        int c = t + i*256;
        orow[c] = (v[i] - mu) * r * g[c] + beta[c];
    }
}

// ---------------- Generic NN SGEMM: 128x64 tile, BK=16, 256 thr, 8x4/thread ------
// MODE 0: C = acc            MODE 1: C = acc + bias[c] + res[r,c]
// MODE 2: C = relu(acc + bias[c])
// PVB: batched attention PV; blockIdx.z = b*16+h, pointers offset internally.
template<int MODE, bool PVB>
__global__ void __launch_bounds__(256)
sgemm_nn(const float* __restrict__ A, int lda,
         const float* __restrict__ Bw, int ldb,
         float* __restrict__ C, int ldc, int K,
         const float* __restrict__ bias,
         const float* __restrict__ res, int ldr)
{
    if (PVB) {
        int z = blockIdx.z, b = z >> 4, h = z & 15;
        A  += (size_t)z * SS * SS;                       // P for (b,h)
        Bw += (size_t)b * SS * (2*DD) + DD + h * 64;     // V slice of kv
        C  += (size_t)b * SS * DD + h * 64;              // out (b,s,(h,d))
    }
    __shared__ float As[16][132];   // transposed A tile [k][m], padded
    __shared__ float Bs[16][68];    // B tile [k][n], padded
    int t = threadIdx.x;
    int row0 = blockIdx.y * 128, col0 = blockIdx.x * 64;
    int tr = t >> 4, tc = t & 15;
    float acc[8][4] = {};
    for (int k0 = 0; k0 < K; k0 += 16) {
#pragma unroll
        for (int i = 0; i < 2; i++) {
            int idx = t + i*256;           // 0..511 : 128 rows x 4 float4
            int r = idx >> 2, c4 = idx & 3;
            float4 a = *(const float4*)(A + (size_t)(row0 + r)*lda + k0 + c4*4);
            As[c4*4+0][r] = a.x; As[c4*4+1][r] = a.y;
            As[c4*4+2][r] = a.z; As[c4*4+3][r] = a.w;
        }
        {
            int r = t >> 4, c4 = t & 15;   // 16 rows x 16 float4
            float4 b4 = *(const float4*)(Bw + (size_t)(k0 + r)*ldb + col0 + c4*4);
            *(float4*)&Bs[r][c4*4] = b4;
        }
        __syncthreads();
#pragma unroll
        for (int kk = 0; kk < 16; kk++) {
            float4 x0 = *(const float4*)&As[kk][tr*8];
            float4 x1 = *(const float4*)&As[kk][tr*8 + 4];
            float4 y0 = *(const float4*)&Bs[kk][tc*4];
            float av[8] = {x0.x, x0.y, x0.z, x0.w, x1.x, x1.y, x1.z, x1.w};
            float bv[4] = {y0.x, y0.y, y0.z, y0.w};
#pragma unroll
            for (int i = 0; i < 8; i++)
#pragma unroll
                for (int j = 0; j < 4; j++)
                    acc[i][j] = fmaf(av[i], bv[j], acc[i][j]);
        }
        __syncthreads();
    }
#pragma unroll
    for (int i = 0; i < 8; i++) {
        int r = row0 + tr*8 + i;
        float* crow = C + (size_t)r*ldc + col0 + tc*4;
#pragma unroll
        for (int j = 0; j < 4; j++) {
            int c = col0 + tc*4 + j;
            float v = acc[i][j];
            if (MODE == 1)      v += bias[c] + res[(size_t)r*ldr + c];
            else if (MODE == 2) v  = fmaxf(v + bias[c], 0.f);
            crow[j] = v;
        }
    }
}

// ---------------- Attention scores: P[b,h,n,m] = scale * Q.Kt, K=64 --------------
__global__ void __launch_bounds__(256)
scores_kernel(const float* __restrict__ Q,
              const float* __restrict__ KV,
              float* __restrict__ P)
{
    int z = blockIdx.z, b = z >> 4, h = z & 15;
    const float* Qp = Q  + (size_t)b*SS*DD     + h*64;
    const float* Kp = KV + (size_t)b*SS*(2*DD) + h*64;
    float* Pp = P + (size_t)z*SS*SS;
    int n0 = blockIdx.y * 64, m0 = blockIdx.x * 64;
    __shared__ float Qs[64][68];   // transposed [d][n]
    __shared__ float Ks[64][68];   // transposed [d][m]
    int t = threadIdx.x;
#pragma unroll
    for (int i = 0; i < 4; i++) {
        int idx = t + i*256;       // 0..1023 : 64 rows x 16 float4
        int r = idx >> 4, c4 = idx & 15;
        float4 q = *(const float4*)(Qp + (size_t)(n0 + r)*DD + c4*4);
        Qs[c4*4+0][r] = q.x; Qs[c4*4+1][r] = q.y;
        Qs[c4*4+2][r] = q.z; Qs[c4*4+3][r] = q.w;
        float4 k = *(const float4*)(Kp + (size_t)(m0 + r)*(2*DD) + c4*4);
        Ks[c4*4+0][r] = k.x; Ks[c4*4+1][r] = k.y;
        Ks[c4*4+2][r] = k.z; Ks[c4*4+3][r] = k.w;
    }
    __syncthreads();
    int tr = t >> 4, tc = t & 15;
    float acc[4][4] = {};
#pragma unroll
    for (int kk = 0; kk < 64; kk++) {
        float4 q4 = *(const float4*)&Qs[kk][tr*4];
        float4 k4 = *(const float4*)&Ks[kk][tc*4];
        float qa[4] = {q4.x, q4.y, q4.z, q4.w};
        float ka[4] = {k4.x, k4.y, k4.z, k4.w};
#pragma unroll
        for (int i = 0; i < 4; i++)
#pragma unroll
            for (int j = 0; j < 4; j++)
                acc[i][j] = fmaf(qa[i], ka[j], acc[i][j]);
    }
    const float scale = 0.125f;   // 64^-0.5
#pragma unroll
    for (int i = 0; i < 4; i++) {
        float4 v = make_float4(acc[i][0]*scale, acc[i][1]*scale,
                               acc[i][2]*scale, acc[i][3]*scale);
        *(float4*)(Pp + (size_t)(n0 + tr*4 + i)*SS + m0 + tc*4) = v;
    }
}

// ---------------- Row softmax over m (row length 2048), in place ----------------
__global__ void __launch_bounds__(256)
softmax_kernel(float* __restrict__ P)
{
    size_t row = blockIdx.x;
    float* p = P + row * (size_t)SS;
    int t = threadIdx.x;
    __shared__ float red[32];
    float v[8]; float mx = -1e30f;
#pragma unroll
    for (int i = 0; i < 8; i++) { v[i] = p[t + i*256]; mx = fmaxf(mx, v[i]); }
#pragma unroll
    for (int o = 16; o > 0; o >>= 1) mx = fmaxf(mx, __shfl_xor_sync(0xffffffffu, mx, o));
    if ((t & 31) == 0) red[t >> 5] = mx;
    __syncthreads();
    if (t < 32) {
        float m = (t < 8) ? red[t] : -1e30f;
#pragma unroll
        for (int o = 4; o > 0; o >>= 1) m = fmaxf(m, __shfl_xor_sync(0xffffffffu, m, o));
        red[t] = m;
    }
    __syncthreads();
    mx = red[0];
    __syncthreads();
    float s = 0.f;
#pragma unroll
    for (int i = 0; i < 8; i++) { v[i] = __expf(v[i] - mx); s += v[i]; }
#pragma unroll
    for (int o = 16; o > 0; o >>= 1) s += __shfl_xor_sync(0xffffffffu, s, o);
    if ((t & 31) == 0) red[t >> 5] = s;
    __syncthreads();
    if (t < 32) {
        float m = (t < 8) ? red[t] : 0.f;
#pragma unroll
        for (int o = 4; o > 0; o >>= 1) m += __shfl_xor_sync(0xffffffffu, m, o);
        red[t] = m;
    }
    __syncthreads();
    float inv = 1.f / red[0];
#pragma unroll
    for (int i = 0; i < 8; i++) p[t + i*256] = v[i] * inv;
}

// ---------------- Transpose P(b,h,n,m) -> attn_out(b,n,m,h), coalesced both ways -
__global__ void __launch_bounds__(256)
attn_transpose(const float* __restrict__ P, float* __restrict__ outA)
{
    __shared__ float tbuf[16][65];
    int m0 = blockIdx.x * 64;
    int n  = blockIdx.y;
    int b  = blockIdx.z;
    int t  = threadIdx.x;
#pragma unroll
    for (int i = 0; i < 4; i++) {
        int idx = t + i*256;        // 0..1023
        int h = idx >> 6, m = idx & 63;
        tbuf[h][m] = P[(((size_t)(b*NHH + h))*SS + n)*SS + m0 + m];
    }
    __syncthreads();
    float* op = outA + (((size_t)b*SS + n)*SS + m0) * NHH;
#pragma unroll
    for (int i = 0; i < 4; i++) {
        int idx = t + i*256;        // idx = m*16 + h
        int m = idx >> 4, h = idx & 15;
        op[idx] = tbuf[h][m];
    }
}

// ---------------- launcher -------------------------------------------------------
extern "C" void kernel_launch(void* const* d_in, const int* in_sizes, int n_in,
                              void* d_out, int out_size)
{
    const float* x    = (const float*)d_in[0];
    const float* ln1g = (const float*)d_in[1];
    const float* ln1b = (const float*)d_in[2];
    const float* wq   = (const float*)d_in[3];
    const float* wkv  = (const float*)d_in[4];
    const float* wo   = (const float*)d_in[5];
    const float* bo   = (const float*)d_in[6];
    const float* ln2g = (const float*)d_in[7];
    const float* ln2b = (const float*)d_in[8];
    const float* w1   = (const float*)d_in[9];
    const float* b1   = (const float*)d_in[10];
    const float* w2   = (const float*)d_in[11];
    const float* b2   = (const float*)d_in[12];

    float* out = (float*)d_out;
    size_t attn_elems = (size_t)BB * SS * SS * NHH;
    float* out_attn = out + ((size_t)out_size - attn_elems);

    float *hp, *qp, *kvp, *aop, *ffp, *Pp;
    cudaGetSymbolAddress((void**)&hp,  g_h);
    cudaGetSymbolAddress((void**)&qp,  g_q);
    cudaGetSymbolAddress((void**)&kvp, g_kv);
    cudaGetSymbolAddress((void**)&aop, g_ao);
    cudaGetSymbolAddress((void**)&ffp, g_ff);
    cudaGetSymbolAddress((void**)&Pp,  g_P);
    float* x2p = qp;   // reuse: Q dead after scores
    float* h2p = hp;   // reuse: LN1 out dead after q/kv gemms

    // 1) LN1
    ln_kernel<<<RR, 256>>>(x, ln1g, ln1b, hp);
    // 2) Q = h @ wq            (4096 x 1024 x 1024)
    sgemm_nn<0, false><<<dim3(DD/64, RR/128, 1), 256>>>(hp, DD, wq, DD, qp, DD, DD,
                                                        nullptr, nullptr, 0);
    // 3) KV = h @ wkv          (4096 x 2048 x 1024)
    sgemm_nn<0, false><<<dim3(2*DD/64, RR/128, 1), 256>>>(hp, DD, wkv, 2*DD, kvp, 2*DD, DD,
                                                          nullptr, nullptr, 0);
    // 4) scores -> P           (per (b,h): 2048 x 2048 x 64)
    scores_kernel<<<dim3(SS/64, SS/64, BB*NHH), 256>>>(qp, kvp, Pp);
    // 5) softmax rows of P
    softmax_kernel<<<BB*NHH*SS, 256>>>(Pp);
    // 6) O = P @ V             (per (b,h): 2048 x 64 x 2048)
    sgemm_nn<0, true><<<dim3(1, SS/128, BB*NHH), 256>>>(Pp, SS, kvp, 2*DD, aop, DD, SS,
                                                        nullptr, nullptr, 0);
    // 7) attn output (b,n,m,h) layout
    attn_transpose<<<dim3(SS/64, SS, BB), 256>>>(Pp, out_attn);
    // 8) x2 = x + O @ wo + bo  (4096 x 1024 x 1024)   [x2p aliases qp; Q is dead]
    sgemm_nn<1, false><<<dim3(DD/64, RR/128, 1), 256>>>(aop, DD, wo, DD, x2p, DD, DD,
                                                        bo, x, DD);
    // 9) LN2                                           [h2p aliases hp; h is dead]
    ln_kernel<<<RR, 256>>>(x2p, ln2g, ln2b, h2p);
    // 10) FF1 = relu(h2 @ w1 + b1)   (4096 x 4096 x 1024)
    sgemm_nn<2, false><<<dim3(FFF/64, RR/128, 1), 256>>>(h2p, DD, w1, FFF, ffp, FFF, DD,
                                                         b1, nullptr, 0);
    // 11) out = x2 + FF1 @ w2 + b2   (4096 x 1024 x 4096)
    sgemm_nn<1, false><<<dim3(DD/64, RR/128, 1), 256>>>(ffp, FFF, w2, DD, out, DD, FFF,
                                                        b2, x2p, DD);
}

// round 3
// speedup vs baseline: 2.2835x; 2.2835x over previous
#include <cuda_runtime.h>
#include <math.h>
#include <stdint.h>

#define BB 2
#define SS 2048
#define DD 1024
#define NHH 16
#define HDD 64
#define FFF 4096
#define RR (BB*SS)   // 4096 rows

// ---------------- scratch (no allocs allowed; __device__ globals) ----------------
__device__ float g_h [RR*DD];                       // LN1 out  / LN2 out
__device__ float g_q [RR*DD];                       // Q        / x2
__device__ float g_kv[RR*2*DD];                     // K|V
__device__ float g_ao[RR*DD];                       // attn output (b,s,(h,d))
__device__ float g_ff[(size_t)RR*FFF];              // FFN hidden
__device__ float g_P [(size_t)BB*NHH*SS*SS];        // softmax probs (b,h,n,m)

// ---------------- helpers --------------------------------------------------------
__device__ __forceinline__ uint32_t f2tf(float x) {
    uint32_t r;
    asm("cvt.rna.tf32.f32 %0, %1;" : "=r"(r) : "f"(x));
    return r;
}
__device__ __forceinline__ void mma8(float* c, const uint32_t* a, const uint32_t* b) {
    asm volatile(
        "mma.sync.aligned.m16n8k8.row.col.f32.tf32.tf32.f32 "
        "{%0,%1,%2,%3},{%4,%5,%6,%7},{%8,%9},{%0,%1,%2,%3};"
        : "+f"(c[0]), "+f"(c[1]), "+f"(c[2]), "+f"(c[3])
        : "r"(a[0]), "r"(a[1]), "r"(a[2]), "r"(a[3]), "r"(b[0]), "r"(b[1]));
}

// ---------------- tf32 tensor-core GEMM ------------------------------------------
// Tile: 128 x BN, BK=16, 256 threads (8 warps as 2m x 4n), warp tile 64 x BN/4.
// MODE 0: C=acc   1: C=acc+bias[c]+res[r,c]   2: C=relu(acc+bias[c])   3: C=acc*0.125
// BATCH 0: dense NN.  1: scores (per b,h: Q.K^T, NT).  2: PV (per b,h: P.V, NN).
template<int BN, int MODE, int BATCH>
__global__ void __launch_bounds__(256)
mma_gemm(const float* __restrict__ A, int lda,
         const float* __restrict__ B, int ldb,
         float* __restrict__ C, int ldc, int K,
         const float* __restrict__ bias,
         const float* __restrict__ res, int ldr)
{
    constexpr int WN = BN / 4;         // warp n extent
    constexpr int NF = WN / 8;         // n-frags per warp
    constexpr int BSTR = BN + 8;       // Bs row stride (== 8 mod 32 -> conflict-free frags)

    if (BATCH == 1) {                  // scores: A=Q, B=K(slice of KV), C=P
        int z = blockIdx.z, b = z >> 4, h = z & 15;
        A += (size_t)b * SS * DD + h * 64;          lda = DD;
        B += (size_t)b * SS * (2*DD) + h * 64;      ldb = 2*DD;
        C += (size_t)z * SS * SS;                   ldc = SS;
    } else if (BATCH == 2) {           // PV: A=P, B=V(slice of KV), C=ao
        int z = blockIdx.z, b = z >> 4, h = z & 15;
        A += (size_t)z * SS * SS;                   lda = SS;
        B += (size_t)b * SS * (2*DD) + DD + h * 64; ldb = 2*DD;
        C += (size_t)b * SS * DD + h * 64;          ldc = DD;
    }

    __shared__ uint32_t As[128][20];     // [m][k], stride 20
    __shared__ uint32_t Bs[16][BSTR];    // [k][n]

    int tid = threadIdx.x;
    int lane = tid & 31, w = tid >> 5;
    int wm = (w & 1) * 64;
    int wn = (w >> 1) * WN;
    int row0 = blockIdx.y * 128, col0 = blockIdx.x * BN;

    float acc[4][NF][4];
#pragma unroll
    for (int i = 0; i < 4; i++)
#pragma unroll
        for (int j = 0; j < NF; j++)
#pragma unroll
            for (int l = 0; l < 4; l++) acc[i][j][l] = 0.f;

    for (int k0 = 0; k0 < K; k0 += 16) {
        // ---- A tile: 128x16, float4 along k ----
#pragma unroll
        for (int i = 0; i < 2; i++) {
            int idx = tid + i * 256;           // [0,512)
            int m = idx >> 2, k4 = (idx & 3) * 4;
            float4 a = *(const float4*)(A + (size_t)(row0 + m) * lda + k0 + k4);
            As[m][k4 + 0] = f2tf(a.x); As[m][k4 + 1] = f2tf(a.y);
            As[m][k4 + 2] = f2tf(a.z); As[m][k4 + 3] = f2tf(a.w);
        }
        // ---- B tile: 16xBN ----
        if (BATCH == 1) {
            // NT: global rows are n (seq m), cols are k (head dim); transpose into Bs
#pragma unroll
            for (int i = 0; i < BN / 64; i++) {
                int idx = tid + i * 256;       // [0, BN*4)
                int n = idx >> 2, k4 = (idx & 3) * 4;
                float4 b4 = *(const float4*)(B + (size_t)(col0 + n) * ldb + k0 + k4);
                Bs[k4 + 0][n] = f2tf(b4.x); Bs[k4 + 1][n] = f2tf(b4.y);
                Bs[k4 + 2][n] = f2tf(b4.z); Bs[k4 + 3][n] = f2tf(b4.w);
            }
        } else {
            // NN: float4 along n
#pragma unroll
            for (int i = 0; i < BN / 64; i++) {
                int idx = tid + i * 256;       // [0, 16*BN/4)
                int k = idx / (BN / 4), c4 = (idx % (BN / 4)) * 4;
                float4 b4 = *(const float4*)(B + (size_t)(k0 + k) * ldb + col0 + c4);
                Bs[k][c4 + 0] = f2tf(b4.x); Bs[k][c4 + 1] = f2tf(b4.y);
                Bs[k][c4 + 2] = f2tf(b4.z); Bs[k][c4 + 3] = f2tf(b4.w);
            }
        }
        __syncthreads();

#pragma unroll
        for (int ks = 0; ks < 16; ks += 8) {
            uint32_t af[4][4];
#pragma unroll
            for (int mi = 0; mi < 4; mi++) {
                int m = wm + mi * 16 + (lane >> 2);
                int kk = ks + (lane & 3);
                af[mi][0] = As[m][kk];
                af[mi][1] = As[m + 8][kk];
                af[mi][2] = As[m][kk + 4];
                af[mi][3] = As[m + 8][kk + 4];
            }
            uint32_t bf[NF][2];
#pragma unroll
            for (int ni = 0; ni < NF; ni++) {
                int n = wn + ni * 8 + (lane >> 2);
                int kb = ks + (lane & 3);
                bf[ni][0] = Bs[kb][n];
                bf[ni][1] = Bs[kb + 4][n];
            }
#pragma unroll
            for (int mi = 0; mi < 4; mi++)
#pragma unroll
                for (int ni = 0; ni < NF; ni++)
                    mma8(acc[mi][ni], af[mi], bf[ni]);
        }
        __syncthreads();
    }

    // ---- epilogue ----
#pragma unroll
    for (int mi = 0; mi < 4; mi++) {
#pragma unroll
        for (int ni = 0; ni < NF; ni++) {
            int r = row0 + wm + mi * 16 + (lane >> 2);
            int c = col0 + wn + ni * 8 + 2 * (lane & 3);
#pragma unroll
            for (int half = 0; half < 2; half++) {
                int rr = r + half * 8;
                float v0 = acc[mi][ni][half * 2 + 0];
                float v1 = acc[mi][ni][half * 2 + 1];
                if (MODE == 1) {
                    v0 += bias[c]     + res[(size_t)rr * ldr + c];
                    v1 += bias[c + 1] + res[(size_t)rr * ldr + c + 1];
                } else if (MODE == 2) {
                    v0 = fmaxf(v0 + bias[c], 0.f);
                    v1 = fmaxf(v1 + bias[c + 1], 0.f);
                } else if (MODE == 3) {
                    v0 *= 0.125f; v1 *= 0.125f;
                }
                *(float2*)(C + (size_t)rr * ldc + c) = make_float2(v0, v1);
            }
        }
    }
}

// ---------------- LayerNorm ------------------------------------------------------
__global__ void __launch_bounds__(256)
ln_kernel(const float* __restrict__ x, const float* __restrict__ g,
          const float* __restrict__ beta, float* __restrict__ out)
{
    __shared__ float red[64];
    int row = blockIdx.x;
    const float* xr = x + (size_t)row*DD;
    float* orow = out + (size_t)row*DD;
    int t = threadIdx.x;
    float v[4]; float s = 0.f, sq = 0.f;
#pragma unroll
    for (int i = 0; i < 4; i++) {
        v[i] = xr[t + i*256];
        s += v[i];
        sq = fmaf(v[i], v[i], sq);
    }
#pragma unroll
    for (int o = 16; o > 0; o >>= 1) {
        s  += __shfl_down_sync(0xffffffffu, s,  o);
        sq += __shfl_down_sync(0xffffffffu, sq, o);
    }
    int lane = t & 31, w = t >> 5;
    if (lane == 0) { red[w] = s; red[w + 32] = sq; }
    __syncthreads();
    if (t == 0) {
        float ts = 0.f, tq = 0.f;
        for (int i = 0; i < 8; i++) { ts += red[i]; tq += red[i + 32]; }
        float mu  = ts * (1.0f / DD);
        float var = tq * (1.0f / DD) - mu * mu;
        red[0] = mu;
        red[1] = rsqrtf(var + 1e-5f);
    }
    __syncthreads();
    float mu = red[0], r = red[1];
#pragma unroll
    for (int i = 0; i < 4; i++) {
        int c = t + i*256;
        orow[c] = (v[i] - mu) * r * g[c] + beta[c];
    }
}

// ---------------- Row softmax over m (row length 2048), in place ----------------
__global__ void __launch_bounds__(256)
softmax_kernel(float* __restrict__ P)
{
    size_t row = blockIdx.x;
    float* p = P + row * (size_t)SS;
    int t = threadIdx.x;
    __shared__ float red[32];
    float v[8]; float mx = -1e30f;
#pragma unroll
    for (int i = 0; i < 8; i++) { v[i] = p[t + i*256]; mx = fmaxf(mx, v[i]); }
#pragma unroll
    for (int o = 16; o > 0; o >>= 1) mx = fmaxf(mx, __shfl_xor_sync(0xffffffffu, mx, o));
    if ((t & 31) == 0) red[t >> 5] = mx;
    __syncthreads();
    if (t < 32) {
        float m = (t < 8) ? red[t] : -1e30f;
#pragma unroll
        for (int o = 4; o > 0; o >>= 1) m = fmaxf(m, __shfl_xor_sync(0xffffffffu, m, o));
        red[t] = m;
    }
    __syncthreads();
    mx = red[0];
    __syncthreads();
    float s = 0.f;
#pragma unroll
    for (int i = 0; i < 8; i++) { v[i] = __expf(v[i] - mx); s += v[i]; }
#pragma unroll
    for (int o = 16; o > 0; o >>= 1) s += __shfl_xor_sync(0xffffffffu, s, o);
    if ((t & 31) == 0) red[t >> 5] = s;
    __syncthreads();
    if (t < 32) {
        float m = (t < 8) ? red[t] : 0.f;
#pragma unroll
        for (int o = 4; o > 0; o >>= 1) m += __shfl_xor_sync(0xffffffffu, m, o);
        red[t] = m;
    }
    __syncthreads();
    float inv = 1.f / red[0];
#pragma unroll
    for (int i = 0; i < 8; i++) p[t + i*256] = v[i] * inv;
}

// ---------------- Transpose P(b,h,n,m) -> attn_out(b,n,m,h) ---------------------
__global__ void __launch_bounds__(256)
attn_transpose(const float* __restrict__ P, float* __restrict__ outA)
{
    __shared__ float tbuf[16][65];
    int m0 = blockIdx.x * 64;
    int n  = blockIdx.y;
    int b  = blockIdx.z;
    int t  = threadIdx.x;
#pragma unroll
    for (int i = 0; i < 4; i++) {
        int idx = t + i*256;        // 0..1023
        int h = idx >> 6, m = idx & 63;
        tbuf[h][m] = P[(((size_t)(b*NHH + h))*SS + n)*SS + m0 + m];
    }
    __syncthreads();
    float* op = outA + (((size_t)b*SS + n)*SS + m0) * NHH;
#pragma unroll
    for (int i = 0; i < 4; i++) {
        int idx = t + i*256;        // idx = m*16 + h
        int m = idx >> 4, h = idx & 15;
        op[idx] = tbuf[h][m];
    }
}

// ---------------- launcher -------------------------------------------------------
extern "C" void kernel_launch(void* const* d_in, const int* in_sizes, int n_in,
                              void* d_out, int out_size)
{
    const float* x    = (const float*)d_in[0];
    const float* ln1g = (const float*)d_in[1];
    const float* ln1b = (const float*)d_in[2];
    const float* wq   = (const float*)d_in[3];
    const float* wkv  = (const float*)d_in[4];
    const float* wo   = (const float*)d_in[5];
    const float* bo   = (const float*)d_in[6];
    const float* ln2g = (const float*)d_in[7];
    const float* ln2b = (const float*)d_in[8];
    const float* w1   = (const float*)d_in[9];
    const float* b1   = (const float*)d_in[10];
    const float* w2   = (const float*)d_in[11];
    const float* b2   = (const float*)d_in[12];

    float* out = (float*)d_out;
    size_t attn_elems = (size_t)BB * SS * SS * NHH;
    float* out_attn = out + ((size_t)out_size - attn_elems);

    float *hp, *qp, *kvp, *aop, *ffp, *Pp;
    cudaGetSymbolAddress((void**)&hp,  g_h);
    cudaGetSymbolAddress((void**)&qp,  g_q);
    cudaGetSymbolAddress((void**)&kvp, g_kv);
    cudaGetSymbolAddress((void**)&aop, g_ao);
    cudaGetSymbolAddress((void**)&ffp, g_ff);
    cudaGetSymbolAddress((void**)&Pp,  g_P);
    float* x2p = qp;   // reuse: Q dead after scores
    float* h2p = hp;   // reuse: LN1 out dead after q/kv gemms

    // 1) LN1
    ln_kernel<<<RR, 256>>>(x, ln1g, ln1b, hp);
    // 2) Q = h @ wq
    mma_gemm<128, 0, 0><<<dim3(DD/128, RR/128, 1), 256>>>(hp, DD, wq, DD, qp, DD, DD,
                                                          nullptr, nullptr, 0);
    // 3) KV = h @ wkv
    mma_gemm<128, 0, 0><<<dim3(2*DD/128, RR/128, 1), 256>>>(hp, DD, wkv, 2*DD, kvp, 2*DD, DD,
                                                            nullptr, nullptr, 0);
    // 4) scores -> P (scaled)
    mma_gemm<128, 3, 1><<<dim3(SS/128, SS/128, BB*NHH), 256>>>(qp, 0, kvp, 0, Pp, 0, HDD,
                                                               nullptr, nullptr, 0);
    // 5) softmax rows of P
    softmax_kernel<<<BB*NHH*SS, 256>>>(Pp);
    // 6) O = P @ V
    mma_gemm<64, 0, 2><<<dim3(1, SS/128, BB*NHH), 256>>>(Pp, 0, kvp, 0, aop, 0, SS,
                                                         nullptr, nullptr, 0);
    // 7) attn output (b,n,m,h) layout
    attn_transpose<<<dim3(SS/64, SS, BB), 256>>>(Pp, out_attn);
    // 8) x2 = x + O @ wo + bo
    mma_gemm<128, 1, 0><<<dim3(DD/128, RR/128, 1), 256>>>(aop, DD, wo, DD, x2p, DD, DD,
                                                          bo, x, DD);
    // 9) LN2
    ln_kernel<<<RR, 256>>>(x2p, ln2g, ln2b, h2p);
    // 10) FF1 = relu(h2 @ w1 + b1)
    mma_gemm<128, 2, 0><<<dim3(FFF/128, RR/128, 1), 256>>>(h2p, DD, w1, FFF, ffp, FFF, DD,
                                                           b1, nullptr, 0);
    // 11) out = x2 + FF1 @ w2 + b2
    mma_gemm<128, 1, 0><<<dim3(DD/128, RR/128, 1), 256>>>(ffp, FFF, w2, DD, out, DD, FFF,
                                                          b2, x2p, DD);
}

// round 4
// speedup vs baseline: 2.4752x; 1.0840x over previous
#include <cuda_runtime.h>
#include <math.h>
#include <stdint.h>

#define BB 2
#define SS 2048
#define DD 1024
#define NHH 16
#define HDD 64
#define FFF 4096
#define RR (BB*SS)   // 4096 rows

// ---------------- scratch ---------------------------------------------------------
__device__ float g_h [RR*DD];                       // LN1 out / LN2 out
__device__ float g_q [RR*DD];                       // Q       / x2
__device__ float g_kv[RR*2*DD];                     // K|V
__device__ float g_ao[RR*DD];                       // attn output (b,s,(h,d))
__device__ float g_ff[(size_t)RR*FFF];              // FFN hidden
__device__ float g_P [(size_t)BB*NHH*SS*SS];        // unnormalized exp(scores) (b,h,n,m)
__device__ float g_rs[(size_t)BB*NHH*SS];           // softmax row sums

// ---------------- helpers ---------------------------------------------------------
__device__ __forceinline__ void cpa16(void* dst, const void* src) {
    uint32_t d = (uint32_t)__cvta_generic_to_shared(dst);
    asm volatile("cp.async.ca.shared.global [%0], [%1], 16;" :: "r"(d), "l"(src));
}
__device__ __forceinline__ void cp_commit() { asm volatile("cp.async.commit_group;"); }
template<int N> __device__ __forceinline__ void cp_wait() {
    asm volatile("cp.async.wait_group %0;" :: "n"(N));
}
__device__ __forceinline__ void mma8(float* c, const uint32_t* a, const uint32_t* b) {
    asm volatile(
        "mma.sync.aligned.m16n8k8.row.col.f32.tf32.tf32.f32 "
        "{%0,%1,%2,%3},{%4,%5,%6,%7},{%8,%9},{%0,%1,%2,%3};"
        : "+f"(c[0]), "+f"(c[1]), "+f"(c[2]), "+f"(c[3])
        : "r"(a[0]), "r"(a[1]), "r"(a[2]), "r"(a[3]), "r"(b[0]), "r"(b[1]));
}

// ---------------- dense tf32 GEMM: 128x128 tile, BK=16, cp.async double buffer ----
// MODE 0: C=acc   1: C=acc+bias[c]+res[r,c]   2: C=relu(acc+bias[c])
template<int MODE>
__global__ void __launch_bounds__(256, 2)
mma_gemm(const float* __restrict__ A, int lda,
         const float* __restrict__ B, int ldb,
         float* __restrict__ C, int ldc, int K,
         const float* __restrict__ bias,
         const float* __restrict__ res, int ldr)
{
    __shared__ uint32_t As[2][128*20];   // [m][k] stride 20
    __shared__ uint32_t Bs[2][16*136];   // [k][n] stride 136

    int tid = threadIdx.x, lane = tid & 31, w = tid >> 5;
    int wm = (w & 1) * 64, wn = (w >> 1) * 32;
    int row0 = blockIdx.y * 128, col0 = blockIdx.x * 128;

    float acc[4][4][4];
#pragma unroll
    for (int i = 0; i < 4; i++)
#pragma unroll
        for (int j = 0; j < 4; j++)
#pragma unroll
            for (int l = 0; l < 4; l++) acc[i][j][l] = 0.f;

    int niter = K / 16;
    // prologue loads
    {
#pragma unroll
        for (int i = 0; i < 2; i++) {
            int idx = tid + i*256; int m = idx >> 2, c4 = (idx & 3) * 4;
            cpa16(&As[0][m*20 + c4], A + (size_t)(row0 + m)*lda + c4);
        }
#pragma unroll
        for (int i = 0; i < 2; i++) {
            int idx = tid + i*256; int k = idx >> 5, c4 = (idx & 31) * 4;
            cpa16(&Bs[0][k*136 + c4], B + (size_t)k*ldb + col0 + c4);
        }
        cp_commit();
    }

    for (int it = 0; it < niter; it++) {
        if (it + 1 < niter) {
            int k0 = (it + 1) * 16, nb = (it + 1) & 1;
#pragma unroll
            for (int i = 0; i < 2; i++) {
                int idx = tid + i*256; int m = idx >> 2, c4 = (idx & 3) * 4;
                cpa16(&As[nb][m*20 + c4], A + (size_t)(row0 + m)*lda + k0 + c4);
            }
#pragma unroll
            for (int i = 0; i < 2; i++) {
                int idx = tid + i*256; int k = idx >> 5, c4 = (idx & 31) * 4;
                cpa16(&Bs[nb][k*136 + c4], B + (size_t)(k0 + k)*ldb + col0 + c4);
            }
            cp_commit();
            cp_wait<1>();
        } else {
            cp_wait<0>();
        }
        __syncthreads();
        const uint32_t* Ab = As[it & 1];
        const uint32_t* Bb = Bs[it & 1];
#pragma unroll
        for (int ks = 0; ks < 16; ks += 8) {
            uint32_t af[4][4], bf[4][2];
#pragma unroll
            for (int mi = 0; mi < 4; mi++) {
                int m = wm + mi*16 + (lane >> 2), kk = ks + (lane & 3);
                af[mi][0] = Ab[m*20 + kk];       af[mi][1] = Ab[(m+8)*20 + kk];
                af[mi][2] = Ab[m*20 + kk + 4];   af[mi][3] = Ab[(m+8)*20 + kk + 4];
            }
#pragma unroll
            for (int ni = 0; ni < 4; ni++) {
                int n = wn + ni*8 + (lane >> 2), kb = ks + (lane & 3);
                bf[ni][0] = Bb[kb*136 + n];  bf[ni][1] = Bb[(kb+4)*136 + n];
            }
#pragma unroll
            for (int mi = 0; mi < 4; mi++)
#pragma unroll
                for (int ni = 0; ni < 4; ni++)
                    mma8(acc[mi][ni], af[mi], bf[ni]);
        }
        __syncthreads();
    }

#pragma unroll
    for (int mi = 0; mi < 4; mi++) {
#pragma unroll
        for (int ni = 0; ni < 4; ni++) {
            int r = row0 + wm + mi*16 + (lane >> 2);
            int c = col0 + wn + ni*8 + 2*(lane & 3);
#pragma unroll
            for (int half = 0; half < 2; half++) {
                int rr = r + half*8;
                float v0 = acc[mi][ni][half*2 + 0];
                float v1 = acc[mi][ni][half*2 + 1];
                if (MODE == 1) {
                    v0 += bias[c]   + res[(size_t)rr*ldr + c];
                    v1 += bias[c+1] + res[(size_t)rr*ldr + c + 1];
                } else if (MODE == 2) {
                    v0 = fmaxf(v0 + bias[c], 0.f);
                    v1 = fmaxf(v1 + bias[c+1], 0.f);
                }
                *(float2*)(C + (size_t)rr*ldc + c) = make_float2(v0, v1);
            }
        }
    }
}

// ---------------- fused attention: QK^T + exp + rowsum + PV ----------------------
// grid (S/128, B*NH), 256 threads, 1 CTA/SM (175KB dynamic smem).
// Writes unnormalized E to Eout (b,h,n,m), rowsums to rs_g, normalized O to Og.
__global__ void __launch_bounds__(256)
fused_attn(const float* __restrict__ Q, const float* __restrict__ KV,
           float* __restrict__ Eout, float* __restrict__ rs_g,
           float* __restrict__ Og)
{
    extern __shared__ float sm[];
    float* Qs = sm;                   // [128][68]
    float* Ks = Qs + 128*68;          // [128][68]
    float* Vs = Ks + 128*68;          // [128][72]
    float* Es = Vs + 128*72;          // [128][132]
    float* rs = Es + 128*132;         // [128]
    const uint32_t* Qsu = (const uint32_t*)Qs;
    const uint32_t* Ksu = (const uint32_t*)Ks;
    const uint32_t* Vsu = (const uint32_t*)Vs;
    const uint32_t* Esu = (const uint32_t*)Es;

    int bh = blockIdx.y, b = bh >> 4, h = bh & 15;
    int n0 = blockIdx.x * 128;
    const float* Qp = Q  + (size_t)b*SS*DD     + h*64;
    const float* Kp = KV + (size_t)b*SS*(2*DD) + h*64;
    const float* Vp = Kp + DD;
    float* Ep = Eout + (size_t)bh*SS*SS + (size_t)n0*SS;

    int tid = threadIdx.x, lane = tid & 31, w = tid >> 5;
    int wy = w & 1, wx = w >> 1;      // wy: 64-row half; wx: 32-col quarter (QK) / 16-col quarter (PV)

    if (tid < 128) rs[tid] = 0.f;

    // Q tile + first K,V tiles (async)
#pragma unroll
    for (int i = 0; i < 8; i++) {
        int idx = tid + i*256; int r = idx >> 4, c4 = (idx & 15) * 4;
        cpa16(&Qs[r*68 + c4], Qp + (size_t)(n0 + r)*DD + c4);
    }
#pragma unroll
    for (int i = 0; i < 8; i++) {
        int idx = tid + i*256; int r = idx >> 4, c4 = (idx & 15) * 4;
        cpa16(&Ks[r*68 + c4], Kp + (size_t)r*(2*DD) + c4);
    }
#pragma unroll
    for (int i = 0; i < 8; i++) {
        int idx = tid + i*256; int r = idx >> 4, c4 = (idx & 15) * 4;
        cpa16(&Vs[r*72 + c4], Vp + (size_t)r*(2*DD) + c4);
    }
    cp_commit();

    float acc_o[4][2][4];
#pragma unroll
    for (int i = 0; i < 4; i++)
#pragma unroll
        for (int j = 0; j < 2; j++)
#pragma unroll
            for (int l = 0; l < 4; l++) acc_o[i][j][l] = 0.f;

    for (int it = 0; it < 16; it++) {
        int m0 = it * 128;
        cp_wait<0>();
        __syncthreads();

        // ---- S = Q K^T (128x128, k=64) ----
        float acc_s[4][4][4];
#pragma unroll
        for (int i = 0; i < 4; i++)
#pragma unroll
            for (int j = 0; j < 4; j++)
#pragma unroll
                for (int l = 0; l < 4; l++) acc_s[i][j][l] = 0.f;
#pragma unroll
        for (int ks = 0; ks < 64; ks += 8) {
            uint32_t af[4][4], bf[4][2];
#pragma unroll
            for (int mi = 0; mi < 4; mi++) {
                int n = wy*64 + mi*16 + (lane >> 2), kk = ks + (lane & 3);
                af[mi][0] = Qsu[n*68 + kk];      af[mi][1] = Qsu[(n+8)*68 + kk];
                af[mi][2] = Qsu[n*68 + kk + 4];  af[mi][3] = Qsu[(n+8)*68 + kk + 4];
            }
#pragma unroll
            for (int ni = 0; ni < 4; ni++) {
                int m = wx*32 + ni*8 + (lane >> 2), kk = ks + (lane & 3);
                bf[ni][0] = Ksu[m*68 + kk];  bf[ni][1] = Ksu[m*68 + kk + 4];
            }
#pragma unroll
            for (int mi = 0; mi < 4; mi++)
#pragma unroll
                for (int ni = 0; ni < 4; ni++)
                    mma8(acc_s[mi][ni], af[mi], bf[ni]);
        }

        // ---- E = exp(S*scale); rowsum; store to Es ----
#pragma unroll
        for (int mi = 0; mi < 4; mi++) {
            int r = wy*64 + mi*16 + (lane >> 2);
            float p0 = 0.f, p1 = 0.f;
#pragma unroll
            for (int ni = 0; ni < 4; ni++) {
                int m = wx*32 + ni*8 + 2*(lane & 3);
                float e0 = __expf(acc_s[mi][ni][0] * 0.125f);
                float e1 = __expf(acc_s[mi][ni][1] * 0.125f);
                float e2 = __expf(acc_s[mi][ni][2] * 0.125f);
                float e3 = __expf(acc_s[mi][ni][3] * 0.125f);
                Es[r*132 + m] = e0;       Es[r*132 + m + 1] = e1;
                Es[(r+8)*132 + m] = e2;   Es[(r+8)*132 + m + 1] = e3;
                p0 += e0 + e1; p1 += e2 + e3;
            }
            p0 += __shfl_xor_sync(0xffffffffu, p0, 1);
            p0 += __shfl_xor_sync(0xffffffffu, p0, 2);
            p1 += __shfl_xor_sync(0xffffffffu, p1, 1);
            p1 += __shfl_xor_sync(0xffffffffu, p1, 2);
            if ((lane & 3) == 0) { atomicAdd(&rs[r], p0); atomicAdd(&rs[r+8], p1); }
        }
        __syncthreads();

        // ---- coalesced E tile write to gmem (from smem) ----
        {
            int r = tid >> 1, half = tid & 1;
            const float4* src = (const float4*)&Es[r*132 + half*64];
            float4* dst = (float4*)(Ep + (size_t)r*SS + m0 + half*64);
#pragma unroll
            for (int i = 0; i < 16; i++) dst[i] = src[i];
        }

        // ---- O += E V (128x64, k=128) ----
#pragma unroll
        for (int ks = 0; ks < 128; ks += 8) {
            uint32_t af[4][4], bf[2][2];
#pragma unroll
            for (int mi = 0; mi < 4; mi++) {
                int n = wy*64 + mi*16 + (lane >> 2), kk = ks + (lane & 3);
                af[mi][0] = Esu[n*132 + kk];      af[mi][1] = Esu[(n+8)*132 + kk];
                af[mi][2] = Esu[n*132 + kk + 4];  af[mi][3] = Esu[(n+8)*132 + kk + 4];
            }
#pragma unroll
            for (int ni = 0; ni < 2; ni++) {
                int d = wx*16 + ni*8 + (lane >> 2), kk = ks + (lane & 3);
                bf[ni][0] = Vsu[kk*72 + d];  bf[ni][1] = Vsu[(kk+4)*72 + d];
            }
#pragma unroll
            for (int mi = 0; mi < 4; mi++)
#pragma unroll
                for (int ni = 0; ni < 2; ni++)
                    mma8(acc_o[mi][ni], af[mi], bf[ni]);
        }
        __syncthreads();

        // ---- prefetch next K,V ----
        if (it < 15) {
            int mn = (it + 1) * 128;
#pragma unroll
            for (int i = 0; i < 8; i++) {
                int idx = tid + i*256; int r = idx >> 4, c4 = (idx & 15) * 4;
                cpa16(&Ks[r*68 + c4], Kp + (size_t)(mn + r)*(2*DD) + c4);
            }
#pragma unroll
            for (int i = 0; i < 8; i++) {
                int idx = tid + i*256; int r = idx >> 4, c4 = (idx & 15) * 4;
                cpa16(&Vs[r*72 + c4], Vp + (size_t)(mn + r)*(2*DD) + c4);
            }
            cp_commit();
        }
    }

    // ---- epilogue: rowsums + normalized O ----
    if (tid < 128) rs_g[(size_t)bh*SS + n0 + tid] = rs[tid];
    float* Op = Og + (size_t)b*SS*DD + h*64;
#pragma unroll
    for (int mi = 0; mi < 4; mi++) {
        int r = wy*64 + mi*16 + (lane >> 2);
        float inv0 = 1.f / rs[r], inv1 = 1.f / rs[r+8];
#pragma unroll
        for (int ni = 0; ni < 2; ni++) {
            int d = wx*16 + ni*8 + 2*(lane & 3);
            *(float2*)(Op + (size_t)(n0 + r)*DD + d) =
                make_float2(acc_o[mi][ni][0]*inv0, acc_o[mi][ni][1]*inv0);
            *(float2*)(Op + (size_t)(n0 + r + 8)*DD + d) =
                make_float2(acc_o[mi][ni][2]*inv1, acc_o[mi][ni][3]*inv1);
        }
    }
}

// ---------------- LayerNorm ------------------------------------------------------
__global__ void __launch_bounds__(256)
ln_kernel(const float* __restrict__ x, const float* __restrict__ g,
          const float* __restrict__ beta, float* __restrict__ out)
{
    __shared__ float red[64];
    int row = blockIdx.x;
    const float* xr = x + (size_t)row*DD;
    float* orow = out + (size_t)row*DD;
    int t = threadIdx.x;
    float v[4]; float s = 0.f, sq = 0.f;
#pragma unroll
    for (int i = 0; i < 4; i++) {
        v[i] = xr[t + i*256];
        s += v[i];
        sq = fmaf(v[i], v[i], sq);
    }
#pragma unroll
    for (int o = 16; o > 0; o >>= 1) {
        s  += __shfl_down_sync(0xffffffffu, s,  o);
        sq += __shfl_down_sync(0xffffffffu, sq, o);
    }
    int lane = t & 31, w = t >> 5;
    if (lane == 0) { red[w] = s; red[w + 32] = sq; }
    __syncthreads();
    if (t == 0) {
        float ts = 0.f, tq = 0.f;
        for (int i = 0; i < 8; i++) { ts += red[i]; tq += red[i + 32]; }
        float mu  = ts * (1.0f / DD);
        float var = tq * (1.0f / DD) - mu * mu;
        red[0] = mu;
        red[1] = rsqrtf(var + 1e-5f);
    }
    __syncthreads();
    float mu = red[0], r = red[1];
#pragma unroll
    for (int i = 0; i < 4; i++) {
        int c = t + i*256;
        orow[c] = (v[i] - mu) * r * g[c] + beta[c];
    }
}

// ---------------- Transpose+normalize: E(b,h,n,m)/rowsum -> attn(b,n,m,h) --------
__global__ void __launch_bounds__(256)
attn_transpose(const float* __restrict__ P, const float* __restrict__ rs_g,
               float* __restrict__ outA)
{
    __shared__ float tbuf[16][65];
    __shared__ float invs[16];
    int m0 = blockIdx.x * 64;
    int n  = blockIdx.y;
    int b  = blockIdx.z;
    int t  = threadIdx.x;
    if (t < 16) invs[t] = 1.f / rs_g[((size_t)(b*NHH + t))*SS + n];
#pragma unroll
    for (int i = 0; i < 4; i++) {
        int idx = t + i*256;
        int h = idx >> 6, m = idx & 63;
        tbuf[h][m] = P[(((size_t)(b*NHH + h))*SS + n)*SS + m0 + m];
    }
    __syncthreads();
    float* op = outA + (((size_t)b*SS + n)*SS + m0) * NHH;
#pragma unroll
    for (int i = 0; i < 4; i++) {
        int idx = t + i*256;          // idx = m*16 + h
        int m = idx >> 4, h = idx & 15;
        op[idx] = tbuf[h][m] * invs[h];
    }
}

// ---------------- launcher -------------------------------------------------------
extern "C" void kernel_launch(void* const* d_in, const int* in_sizes, int n_in,
                              void* d_out, int out_size)
{
    const float* x    = (const float*)d_in[0];
    const float* ln1g = (const float*)d_in[1];
    const float* ln1b = (const float*)d_in[2];
    const float* wq   = (const float*)d_in[3];
    const float* wkv  = (const float*)d_in[4];
    const float* wo   = (const float*)d_in[5];
    const float* bo   = (const float*)d_in[6];
    const float* ln2g = (const float*)d_in[7];
    const float* ln2b = (const float*)d_in[8];
    const float* w1   = (const float*)d_in[9];
    const float* b1   = (const float*)d_in[10];
    const float* w2   = (const float*)d_in[11];
    const float* b2   = (const float*)d_in[12];

    float* out = (float*)d_out;
    size_t attn_elems = (size_t)BB * SS * SS * NHH;
    float* out_attn = out + ((size_t)out_size - attn_elems);

    float *hp, *qp, *kvp, *aop, *ffp, *Pp, *rsp;
    cudaGetSymbolAddress((void**)&hp,  g_h);
    cudaGetSymbolAddress((void**)&qp,  g_q);
    cudaGetSymbolAddress((void**)&kvp, g_kv);
    cudaGetSymbolAddress((void**)&aop, g_ao);
    cudaGetSymbolAddress((void**)&ffp, g_ff);
    cudaGetSymbolAddress((void**)&Pp,  g_P);
    cudaGetSymbolAddress((void**)&rsp, g_rs);
    float* x2p = qp;   // reuse: Q dead after fused_attn
    float* h2p = hp;   // reuse: LN1 out dead after q/kv gemms

    static int smem_set = 0;
    int attn_smem = (128*68 + 128*68 + 128*72 + 128*132 + 128) * 4;
    if (!smem_set) {
        cudaFuncSetAttribute(fused_attn, cudaFuncAttributeMaxDynamicSharedMemorySize,
                             attn_smem);
        smem_set = 1;
    }

    // 1) LN1
    ln_kernel<<<RR, 256>>>(x, ln1g, ln1b, hp);
    // 2) Q = h @ wq
    mma_gemm<0><<<dim3(DD/128, RR/128), 256>>>(hp, DD, wq, DD, qp, DD, DD,
                                               nullptr, nullptr, 0);
    // 3) KV = h @ wkv
    mma_gemm<0><<<dim3(2*DD/128, RR/128), 256>>>(hp, DD, wkv, 2*DD, kvp, 2*DD, DD,
                                                 nullptr, nullptr, 0);
    // 4) fused attention: E (unnormalized), rowsums, O
    fused_attn<<<dim3(SS/128, BB*NHH), 256, attn_smem>>>(qp, kvp, Pp, rsp, aop);
    // 5) attn output (b,n,m,h), normalized
    attn_transpose<<<dim3(SS/64, SS, BB), 256>>>(Pp, rsp, out_attn);
    // 6) x2 = x + O @ wo + bo
    mma_gemm<1><<<dim3(DD/128, RR/128), 256>>>(aop, DD, wo, DD, x2p, DD, DD,
                                               bo, x, DD);
    // 7) LN2
    ln_kernel<<<RR, 256>>>(x2p, ln2g, ln2b, h2p);
    // 8) FF1 = relu(h2 @ w1 + b1)
    mma_gemm<2><<<dim3(FFF/128, RR/128), 256>>>(h2p, DD, w1, FFF, ffp, FFF, DD,
                                                b1, nullptr, 0);
    // 9) out = x2 + FF1 @ w2 + b2
    mma_gemm<1><<<dim3(DD/128, RR/128), 256>>>(ffp, FFF, w2, DD, out, DD, FFF,
                                               b2, x2p, DD);
}

// round 5
// speedup vs baseline: 2.5167x; 1.0167x over previous
#include <cuda_runtime.h>
#include <math.h>
#include <stdint.h>

#define BB 2
#define SS 2048
#define DD 1024
#define NHH 16
#define HDD 64
#define FFF 4096
#define RR (BB*SS)   // 4096 rows

// ---------------- scratch ---------------------------------------------------------
__device__ float g_h [RR*DD];                       // LN1 out / LN2 out
__device__ float g_q [RR*DD];                       // Q       / x2
__device__ float g_kv[RR*2*DD];                     // K|V
__device__ float g_ao[RR*DD];                       // attn output (b,s,(h,d))
__device__ float g_ff[(size_t)RR*FFF];              // FFN hidden
__device__ float g_P [(size_t)BB*NHH*SS*SS];        // unnormalized exp(scores) (b,h,n,m)
__device__ float g_rs[(size_t)BB*NHH*SS];           // softmax row sums

// ---------------- helpers ---------------------------------------------------------
__device__ __forceinline__ void cpa16(void* dst, const void* src) {
    uint32_t d = (uint32_t)__cvta_generic_to_shared(dst);
    asm volatile("cp.async.ca.shared.global [%0], [%1], 16;" :: "r"(d), "l"(src));
}
__device__ __forceinline__ void cp_commit() { asm volatile("cp.async.commit_group;"); }
template<int N> __device__ __forceinline__ void cp_wait() {
    asm volatile("cp.async.wait_group %0;" :: "n"(N));
}
__device__ __forceinline__ uint32_t f2tf(float x) {
    uint32_t r;
    asm("cvt.rna.tf32.f32 %0, %1;" : "=r"(r) : "f"(x));
    return r;
}
__device__ __forceinline__ uint32_t f2tfu(uint32_t x) {
    uint32_t r;
    asm("cvt.rna.tf32.f32 %0, %1;" : "=r"(r) : "f"(__uint_as_float(x)));
    return r;
}
__device__ __forceinline__ void mma8(float* c, const uint32_t* a, const uint32_t* b) {
    asm volatile(
        "mma.sync.aligned.m16n8k8.row.col.f32.tf32.tf32.f32 "
        "{%0,%1,%2,%3},{%4,%5,%6,%7},{%8,%9},{%0,%1,%2,%3};"
        : "+f"(c[0]), "+f"(c[1]), "+f"(c[2]), "+f"(c[3])
        : "r"(a[0]), "r"(a[1]), "r"(a[2]), "r"(a[3]), "r"(b[0]), "r"(b[1]));
}

// ---------------- dense tf32 GEMM: 128x128 tile, BK=16, cp.async double buffer ----
// MODE 0: C=acc   1: C=acc+bias[c]+res[r,c]   2: C=relu(acc+bias[c])
template<int MODE>
__global__ void __launch_bounds__(256, 2)
mma_gemm(const float* __restrict__ A, int lda,
         const float* __restrict__ B, int ldb,
         float* __restrict__ C, int ldc, int K,
         const float* __restrict__ bias,
         const float* __restrict__ res, int ldr)
{
    __shared__ uint32_t As[2][128*20];   // [m][k] stride 20
    __shared__ uint32_t Bs[2][16*136];   // [k][n] stride 136

    int tid = threadIdx.x, lane = tid & 31, w = tid >> 5;
    int wm = (w & 1) * 64, wn = (w >> 1) * 32;
    int row0 = blockIdx.y * 128, col0 = blockIdx.x * 128;

    float acc[4][4][4];
#pragma unroll
    for (int i = 0; i < 4; i++)
#pragma unroll
        for (int j = 0; j < 4; j++)
#pragma unroll
            for (int l = 0; l < 4; l++) acc[i][j][l] = 0.f;

    int niter = K / 16;
    {
#pragma unroll
        for (int i = 0; i < 2; i++) {
            int idx = tid + i*256; int m = idx >> 2, c4 = (idx & 3) * 4;
            cpa16(&As[0][m*20 + c4], A + (size_t)(row0 + m)*lda + c4);
        }
#pragma unroll
        for (int i = 0; i < 2; i++) {
            int idx = tid + i*256; int k = idx >> 5, c4 = (idx & 31) * 4;
            cpa16(&Bs[0][k*136 + c4], B + (size_t)k*ldb + col0 + c4);
        }
        cp_commit();
    }

    for (int it = 0; it < niter; it++) {
        if (it + 1 < niter) {
            int k0 = (it + 1) * 16, nb = (it + 1) & 1;
#pragma unroll
            for (int i = 0; i < 2; i++) {
                int idx = tid + i*256; int m = idx >> 2, c4 = (idx & 3) * 4;
                cpa16(&As[nb][m*20 + c4], A + (size_t)(row0 + m)*lda + k0 + c4);
            }
#pragma unroll
            for (int i = 0; i < 2; i++) {
                int idx = tid + i*256; int k = idx >> 5, c4 = (idx & 31) * 4;
                cpa16(&Bs[nb][k*136 + c4], B + (size_t)(k0 + k)*ldb + col0 + c4);
            }
            cp_commit();
            cp_wait<1>();
        } else {
            cp_wait<0>();
        }
        __syncthreads();
        const uint32_t* Ab = As[it & 1];
        const uint32_t* Bb = Bs[it & 1];
#pragma unroll
        for (int ks = 0; ks < 16; ks += 8) {
            uint32_t af[4][4], bf[4][2];
#pragma unroll
            for (int mi = 0; mi < 4; mi++) {
                int m = wm + mi*16 + (lane >> 2), kk = ks + (lane & 3);
                af[mi][0] = f2tfu(Ab[m*20 + kk]);      af[mi][1] = f2tfu(Ab[(m+8)*20 + kk]);
                af[mi][2] = f2tfu(Ab[m*20 + kk + 4]);  af[mi][3] = f2tfu(Ab[(m+8)*20 + kk + 4]);
            }
#pragma unroll
            for (int ni = 0; ni < 4; ni++) {
                int n = wn + ni*8 + (lane >> 2), kb = ks + (lane & 3);
                bf[ni][0] = f2tfu(Bb[kb*136 + n]);  bf[ni][1] = f2tfu(Bb[(kb+4)*136 + n]);
            }
#pragma unroll
            for (int mi = 0; mi < 4; mi++)
#pragma unroll
                for (int ni = 0; ni < 4; ni++)
                    mma8(acc[mi][ni], af[mi], bf[ni]);
        }
        __syncthreads();
    }

#pragma unroll
    for (int mi = 0; mi < 4; mi++) {
#pragma unroll
        for (int ni = 0; ni < 4; ni++) {
            int r = row0 + wm + mi*16 + (lane >> 2);
            int c = col0 + wn + ni*8 + 2*(lane & 3);
#pragma unroll
            for (int half = 0; half < 2; half++) {
                int rr = r + half*8;
                float v0 = acc[mi][ni][half*2 + 0];
                float v1 = acc[mi][ni][half*2 + 1];
                if (MODE == 1) {
                    v0 += bias[c]   + res[(size_t)rr*ldr + c];
                    v1 += bias[c+1] + res[(size_t)rr*ldr + c + 1];
                } else if (MODE == 2) {
                    v0 = fmaxf(v0 + bias[c], 0.f);
                    v1 = fmaxf(v1 + bias[c+1], 0.f);
                }
                *(float2*)(C + (size_t)rr*ldc + c) = make_float2(v0, v1);
            }
        }
    }
}

// ---------------- fused attention v2: 512 thr, 64-row K/V tiles, double buffered --
// grid (S/128, B*NH). Q tile 128 rows; 32 iters of 64 keys.
// Writes rounded unnormalized E to Eout (b,h,n,m), rowsums to rs_g, normalized O.
__global__ void __launch_bounds__(512)
fused_attn(const float* __restrict__ Q, const float* __restrict__ KV,
           float* __restrict__ Eout, float* __restrict__ rs_g,
           float* __restrict__ Og)
{
    extern __shared__ float sm[];
    float* Qs = sm;                    // [128][68]
    float* Ks = Qs + 128*68;           // [2][64][68]
    float* Vs = Ks + 2*64*68;          // [2][64][72]
    float* Es = Vs + 2*64*72;          // [128][68]
    float* rs = Es + 128*68;           // [128]
    const uint32_t* Qsu = (const uint32_t*)Qs;
    const uint32_t* Esu = (const uint32_t*)Es;

    int bh = blockIdx.y, b = bh >> 4, h = bh & 15;
    int n0 = blockIdx.x * 128;
    const float* Qp = Q  + (size_t)b*SS*DD     + h*64;
    const float* Kp = KV + (size_t)b*SS*(2*DD) + h*64;
    const float* Vp = Kp + DD;
    float* Ep = Eout + (size_t)bh*SS*SS + (size_t)n0*SS;

    int tid = threadIdx.x, lane = tid & 31, w = tid >> 5;
    int wy = w & 3, wx = w >> 2;    // wy: 32-row group of 128; wx: 16-col group of 64

    if (tid < 128) rs[tid] = 0.f;

    // Q tile (128x16 float4) + K/V tile 0
#pragma unroll
    for (int i = 0; i < 4; i++) {
        int idx = tid + i*512; int r = idx >> 4, c4 = (idx & 15) * 4;
        cpa16(&Qs[r*68 + c4], Qp + (size_t)(n0 + r)*DD + c4);
    }
#pragma unroll
    for (int i = 0; i < 2; i++) {
        int idx = tid + i*512; int r = idx >> 4, c4 = (idx & 15) * 4;
        cpa16(&Ks[r*68 + c4], Kp + (size_t)r*(2*DD) + c4);
        cpa16(&Vs[r*72 + c4], Vp + (size_t)r*(2*DD) + c4);
    }
    cp_commit();
    // K/V tile 1
#pragma unroll
    for (int i = 0; i < 2; i++) {
        int idx = tid + i*512; int r = idx >> 4, c4 = (idx & 15) * 4;
        cpa16(&Ks[64*68 + r*68 + c4], Kp + (size_t)(64 + r)*(2*DD) + c4);
        cpa16(&Vs[64*72 + r*72 + c4], Vp + (size_t)(64 + r)*(2*DD) + c4);
    }
    cp_commit();

    float acc_o[2][2][4];
#pragma unroll
    for (int i = 0; i < 2; i++)
#pragma unroll
        for (int j = 0; j < 2; j++)
#pragma unroll
            for (int l = 0; l < 4; l++) acc_o[i][j][l] = 0.f;

    for (int it = 0; it < 32; it++) {
        int buf = it & 1;
        int m0 = it * 64;
        if (it + 1 < 32) cp_wait<1>(); else cp_wait<0>();
        __syncthreads();
        if (it == 0) {
            // one-time in-place tf32 rounding of Q
#pragma unroll
            for (int i = 0; i < 17; i++) {
                int idx = tid + i*512;
                Qs[idx] = __uint_as_float(f2tf(Qs[idx]));
            }
            __syncthreads();
        }
        const uint32_t* Kb = (const uint32_t*)(Ks + buf*64*68);
        const uint32_t* Vb = (const uint32_t*)(Vs + buf*64*72);

        // ---- S = Q K^T : 128(n) x 64(m), k=64 ----
        float acc_s[2][2][4];
#pragma unroll
        for (int i = 0; i < 2; i++)
#pragma unroll
            for (int j = 0; j < 2; j++)
#pragma unroll
                for (int l = 0; l < 4; l++) acc_s[i][j][l] = 0.f;
#pragma unroll
        for (int ks = 0; ks < 64; ks += 8) {
            uint32_t af[2][4], bf[2][2];
#pragma unroll
            for (int mi = 0; mi < 2; mi++) {
                int n = wy*32 + mi*16 + (lane >> 2), kk = ks + (lane & 3);
                af[mi][0] = Qsu[n*68 + kk];      af[mi][1] = Qsu[(n+8)*68 + kk];
                af[mi][2] = Qsu[n*68 + kk + 4];  af[mi][3] = Qsu[(n+8)*68 + kk + 4];
            }
#pragma unroll
            for (int ni = 0; ni < 2; ni++) {
                int m = wx*16 + ni*8 + (lane >> 2), kk = ks + (lane & 3);
                bf[ni][0] = f2tfu(Kb[m*68 + kk]);  bf[ni][1] = f2tfu(Kb[m*68 + kk + 4]);
            }
#pragma unroll
            for (int mi = 0; mi < 2; mi++)
#pragma unroll
                for (int ni = 0; ni < 2; ni++)
                    mma8(acc_s[mi][ni], af[mi], bf[ni]);
        }

        // ---- E = exp(S/8), rounded to tf32; rowsum; store to Es ----
#pragma unroll
        for (int mi = 0; mi < 2; mi++) {
            int r = wy*32 + mi*16 + (lane >> 2);
            float p0 = 0.f, p1 = 0.f;
#pragma unroll
            for (int ni = 0; ni < 2; ni++) {
                int m = wx*16 + ni*8 + 2*(lane & 3);
                float e0 = __expf(acc_s[mi][ni][0] * 0.125f);
                float e1 = __expf(acc_s[mi][ni][1] * 0.125f);
                float e2 = __expf(acc_s[mi][ni][2] * 0.125f);
                float e3 = __expf(acc_s[mi][ni][3] * 0.125f);
                e0 = __uint_as_float(f2tf(e0)); e1 = __uint_as_float(f2tf(e1));
                e2 = __uint_as_float(f2tf(e2)); e3 = __uint_as_float(f2tf(e3));
                *(float2*)&Es[r*68 + m]     = make_float2(e0, e1);
                *(float2*)&Es[(r+8)*68 + m] = make_float2(e2, e3);
                p0 += e0 + e1; p1 += e2 + e3;
            }
            p0 += __shfl_xor_sync(0xffffffffu, p0, 1);
            p0 += __shfl_xor_sync(0xffffffffu, p0, 2);
            p1 += __shfl_xor_sync(0xffffffffu, p1, 1);
            p1 += __shfl_xor_sync(0xffffffffu, p1, 2);
            if ((lane & 3) == 0) { atomicAdd(&rs[r], p0); atomicAdd(&rs[r+8], p1); }
        }
        __syncthreads();

        // ---- coalesced E tile write (128 x 64) ----
        {
            int r = tid >> 2, q = (tid & 3) * 4;
            const float4* src = (const float4*)&Es[r*68];
            float4* dst = (float4*)(Ep + (size_t)r*SS + m0);
#pragma unroll
            for (int j = 0; j < 4; j++) dst[q + j] = src[q + j];
        }

        // ---- O += E V : 128(n) x 64(d), k=64 ----
#pragma unroll
        for (int ks = 0; ks < 64; ks += 8) {
            uint32_t af[2][4], bf[2][2];
#pragma unroll
            for (int mi = 0; mi < 2; mi++) {
                int n = wy*32 + mi*16 + (lane >> 2), kk = ks + (lane & 3);
                af[mi][0] = Esu[n*68 + kk];      af[mi][1] = Esu[(n+8)*68 + kk];
                af[mi][2] = Esu[n*68 + kk + 4];  af[mi][3] = Esu[(n+8)*68 + kk + 4];
            }
#pragma unroll
            for (int ni = 0; ni < 2; ni++) {
                int d = wx*16 + ni*8 + (lane >> 2), kk = ks + (lane & 3);
                bf[ni][0] = f2tfu(Vb[kk*72 + d]);  bf[ni][1] = f2tfu(Vb[(kk+4)*72 + d]);
            }
#pragma unroll
            for (int mi = 0; mi < 2; mi++)
#pragma unroll
                for (int ni = 0; ni < 2; ni++)
                    mma8(acc_o[mi][ni], af[mi], bf[ni]);
        }
        __syncthreads();

        // ---- prefetch K/V tile it+2 into buf ----
        if (it + 2 < 32) {
            int mn = (it + 2) * 64;
#pragma unroll
            for (int i = 0; i < 2; i++) {
                int idx = tid + i*512; int r = idx >> 4, c4 = (idx & 15) * 4;
                cpa16(&Ks[buf*64*68 + r*68 + c4], Kp + (size_t)(mn + r)*(2*DD) + c4);
                cpa16(&Vs[buf*64*72 + r*72 + c4], Vp + (size_t)(mn + r)*(2*DD) + c4);
            }
            cp_commit();
        }
    }

    // ---- epilogue ----
    if (tid < 128) rs_g[(size_t)bh*SS + n0 + tid] = rs[tid];
    float* Op = Og + (size_t)b*SS*DD + h*64;
#pragma unroll
    for (int mi = 0; mi < 2; mi++) {
        int r = wy*32 + mi*16 + (lane >> 2);
        float inv0 = 1.f / rs[r], inv1 = 1.f / rs[r+8];
#pragma unroll
        for (int ni = 0; ni < 2; ni++) {
            int d = wx*16 + ni*8 + 2*(lane & 3);
            *(float2*)(Op + (size_t)(n0 + r)*DD + d) =
                make_float2(acc_o[mi][ni][0]*inv0, acc_o[mi][ni][1]*inv0);
            *(float2*)(Op + (size_t)(n0 + r + 8)*DD + d) =
                make_float2(acc_o[mi][ni][2]*inv1, acc_o[mi][ni][3]*inv1);
        }
    }
}

// ---------------- LayerNorm ------------------------------------------------------
__global__ void __launch_bounds__(256)
ln_kernel(const float* __restrict__ x, const float* __restrict__ g,
          const float* __restrict__ beta, float* __restrict__ out)
{
    __shared__ float red[64];
    int row = blockIdx.x;
    const float* xr = x + (size_t)row*DD;
    float* orow = out + (size_t)row*DD;
    int t = threadIdx.x;
    float v[4]; float s = 0.f, sq = 0.f;
#pragma unroll
    for (int i = 0; i < 4; i++) {
        v[i] = xr[t + i*256];
        s += v[i];
        sq = fmaf(v[i], v[i], sq);
    }
#pragma unroll
    for (int o = 16; o > 0; o >>= 1) {
        s  += __shfl_down_sync(0xffffffffu, s,  o);
        sq += __shfl_down_sync(0xffffffffu, sq, o);
    }
    int lane = t & 31, w = t >> 5;
    if (lane == 0) { red[w] = s; red[w + 32] = sq; }
    __syncthreads();
    if (t == 0) {
        float ts = 0.f, tq = 0.f;
        for (int i = 0; i < 8; i++) { ts += red[i]; tq += red[i + 32]; }
        float mu  = ts * (1.0f / DD);
        float var = tq * (1.0f / DD) - mu * mu;
        red[0] = mu;
        red[1] = rsqrtf(var + 1e-5f);
    }
    __syncthreads();
    float mu = red[0], r = red[1];
#pragma unroll
    for (int i = 0; i < 4; i++) {
        int c = t + i*256;
        orow[c] = (v[i] - mu) * r * g[c] + beta[c];
    }
}

// ---------------- Transpose+normalize: E(b,h,n,m)/rowsum -> attn(b,n,m,h) --------
__global__ void __launch_bounds__(256)
attn_transpose(const float* __restrict__ P, const float* __restrict__ rs_g,
               float* __restrict__ outA)
{
    __shared__ float tbuf[16][130];
    __shared__ float invs[16];
    int m0 = blockIdx.x * 128;
    int n  = blockIdx.y;
    int b  = blockIdx.z;
    int t  = threadIdx.x;
    if (t < 16) invs[t] = 1.f / rs_g[((size_t)(b*NHH + t))*SS + n];
#pragma unroll
    for (int i = 0; i < 8; i++) {
        int idx = t + i*256;          // 0..2047
        int h = idx >> 7, m = idx & 127;
        tbuf[h][m] = P[(((size_t)(b*NHH + h))*SS + n)*SS + m0 + m];
    }
    __syncthreads();
    float* op = outA + (((size_t)b*SS + n)*SS + m0) * NHH;
#pragma unroll
    for (int i = 0; i < 8; i++) {
        int idx = t + i*256;          // idx = m*16 + h
        int m = idx >> 4, h = idx & 15;
        op[idx] = tbuf[h][m] * invs[h];
    }
}

// ---------------- launcher -------------------------------------------------------
extern "C" void kernel_launch(void* const* d_in, const int* in_sizes, int n_in,
                              void* d_out, int out_size)
{
    const float* x    = (const float*)d_in[0];
    const float* ln1g = (const float*)d_in[1];
    const float* ln1b = (const float*)d_in[2];
    const float* wq   = (const float*)d_in[3];
    const float* wkv  = (const float*)d_in[4];
    const float* wo   = (const float*)d_in[5];
    const float* bo   = (const float*)d_in[6];
    const float* ln2g = (const float*)d_in[7];
    const float* ln2b = (const float*)d_in[8];
    const float* w1   = (const float*)d_in[9];
    const float* b1   = (const float*)d_in[10];
    const float* w2   = (const float*)d_in[11];
    const float* b2   = (const float*)d_in[12];

    float* out = (float*)d_out;
    size_t attn_elems = (size_t)BB * SS * SS * NHH;
    float* out_attn = out + ((size_t)out_size - attn_elems);

    float *hp, *qp, *kvp, *aop, *ffp, *Pp, *rsp;
    cudaGetSymbolAddress((void**)&hp,  g_h);
    cudaGetSymbolAddress((void**)&qp,  g_q);
    cudaGetSymbolAddress((void**)&kvp, g_kv);
    cudaGetSymbolAddress((void**)&aop, g_ao);
    cudaGetSymbolAddress((void**)&ffp, g_ff);
    cudaGetSymbolAddress((void**)&Pp,  g_P);
    cudaGetSymbolAddress((void**)&rsp, g_rs);
    float* x2p = qp;   // reuse: Q dead after fused_attn
    float* h2p = hp;   // reuse: LN1 out dead after q/kv gemms

    static int smem_set = 0;
    int attn_smem = (128*68 + 2*64*68 + 2*64*72 + 128*68 + 128) * 4;  // 141824 B
    if (!smem_set) {
        cudaFuncSetAttribute(fused_attn, cudaFuncAttributeMaxDynamicSharedMemorySize,
                             attn_smem);
        smem_set = 1;
    }

    // 1) LN1
    ln_kernel<<<RR, 256>>>(x, ln1g, ln1b, hp);
    // 2) Q = h @ wq
    mma_gemm<0><<<dim3(DD/128, RR/128), 256>>>(hp, DD, wq, DD, qp, DD, DD,
                                               nullptr, nullptr, 0);
    // 3) KV = h @ wkv
    mma_gemm<0><<<dim3(2*DD/128, RR/128), 256>>>(hp, DD, wkv, 2*DD, kvp, 2*DD, DD,
                                                 nullptr, nullptr, 0);
    // 4) fused attention: E (rounded, unnormalized), rowsums, O
    fused_attn<<<dim3(SS/128, BB*NHH), 512, attn_smem>>>(qp, kvp, Pp, rsp, aop);
    // 5) attn output (b,n,m,h), normalized
    attn_transpose<<<dim3(SS/128, SS, BB), 256>>>(Pp, rsp, out_attn);
    // 6) x2 = x + O @ wo + bo
    mma_gemm<1><<<dim3(DD/128, RR/128), 256>>>(aop, DD, wo, DD, x2p, DD, DD,
                                               bo, x, DD);
    // 7) LN2
    ln_kernel<<<RR, 256>>>(x2p, ln2g, ln2b, h2p);
    // 8) FF1 = relu(h2 @ w1 + b1)
    mma_gemm<2><<<dim3(FFF/128, RR/128), 256>>>(h2p, DD, w1, FFF, ffp, FFF, DD,
                                                b1, nullptr, 0);
    // 9) out = x2 + FF1 @ w2 + b2
    mma_gemm<1><<<dim3(DD/128, RR/128), 256>>>(ffp, FFF, w2, DD, out, DD, FFF,
                                               b2, x2p, DD);
}

// round 6
// speedup vs baseline: 2.5175x; 1.0003x over previous
#include <cuda_runtime.h>
#include <math.h>
#include <stdint.h>

#define BB 2
#define SS 2048
#define DD 1024
#define NHH 16
#define HDD 64
#define FFF 4096
#define RR (BB*SS)   // 4096 rows

// ---------------- scratch ---------------------------------------------------------
__device__ float g_h [RR*DD];                       // LN1 out / LN2 out
__device__ float g_q [RR*DD];                       // Q       / x2
__device__ float g_kv[RR*2*DD];                     // K|V
__device__ float g_ao[RR*DD];                       // attn output (b,s,(h,d))
__device__ float g_ff[(size_t)RR*FFF];              // FFN hidden
__device__ float g_P [(size_t)BB*NHH*SS*SS];        // unnormalized exp(scores) (b,h,n,m)
__device__ float g_rs[(size_t)BB*NHH*SS];           // softmax row sums
__device__ float g_wr[12*1024*1024];                // tf32-rounded weights

// ---------------- helpers ---------------------------------------------------------
__device__ __forceinline__ void cpa16(void* dst, const void* src) {
    uint32_t d = (uint32_t)__cvta_generic_to_shared(dst);
    asm volatile("cp.async.ca.shared.global [%0], [%1], 16;" :: "r"(d), "l"(src));
}
__device__ __forceinline__ void cp_commit() { asm volatile("cp.async.commit_group;"); }
template<int N> __device__ __forceinline__ void cp_wait() {
    asm volatile("cp.async.wait_group %0;" :: "n"(N));
}
__device__ __forceinline__ float f2tf(float x) {
    uint32_t r;
    asm("cvt.rna.tf32.f32 %0, %1;" : "=r"(r) : "f"(x));
    return __uint_as_float(r);
}
__device__ __forceinline__ void mma8(float* c, const uint32_t* a, const uint32_t* b) {
    asm volatile(
        "mma.sync.aligned.m16n8k8.row.col.f32.tf32.tf32.f32 "
        "{%0,%1,%2,%3},{%4,%5,%6,%7},{%8,%9},{%0,%1,%2,%3};"
        : "+f"(c[0]), "+f"(c[1]), "+f"(c[2]), "+f"(c[3])
        : "r"(a[0]), "r"(a[1]), "r"(a[2]), "r"(a[3]), "r"(b[0]), "r"(b[1]));
}

// ---------------- tf32 rounding prep (weights) ------------------------------------
__global__ void __launch_bounds__(256)
round4_kernel(const float* __restrict__ in, float* __restrict__ out, int n4)
{
    int i = blockIdx.x * 256 + threadIdx.x;
    if (i < n4) {
        float4 v = ((const float4*)in)[i];
        v.x = f2tf(v.x); v.y = f2tf(v.y); v.z = f2tf(v.z); v.w = f2tf(v.w);
        ((float4*)out)[i] = v;
    }
}

// ---------------- dense tf32 GEMM: 128x128 tile, BK=16, cp.async double buffer ----
// MODE 0: C=acc   1: C=acc+bias[c]+res[r,c]   2: C=relu(acc+bias[c])
// ROUND: round result to tf32 grid (for values feeding later GEMMs).
template<int MODE, bool ROUND>
__global__ void __launch_bounds__(256, 2)
mma_gemm(const float* __restrict__ A, int lda,
         const float* __restrict__ B, int ldb,
         float* __restrict__ C, int ldc, int K,
         const float* __restrict__ bias,
         const float* __restrict__ res, int ldr)
{
    __shared__ uint32_t As[2][128*20];   // [m][k] stride 20
    __shared__ uint32_t Bs[2][16*136];   // [k][n] stride 136

    int tid = threadIdx.x, lane = tid & 31, w = tid >> 5;
    int wm = (w & 1) * 64, wn = (w >> 1) * 32;
    int row0 = blockIdx.y * 128, col0 = blockIdx.x * 128;

    float acc[4][4][4];
#pragma unroll
    for (int i = 0; i < 4; i++)
#pragma unroll
        for (int j = 0; j < 4; j++)
#pragma unroll
            for (int l = 0; l < 4; l++) acc[i][j][l] = 0.f;

    int niter = K / 16;
    {
#pragma unroll
        for (int i = 0; i < 2; i++) {
            int idx = tid + i*256; int m = idx >> 2, c4 = (idx & 3) * 4;
            cpa16(&As[0][m*20 + c4], A + (size_t)(row0 + m)*lda + c4);
        }
#pragma unroll
        for (int i = 0; i < 2; i++) {
            int idx = tid + i*256; int k = idx >> 5, c4 = (idx & 31) * 4;
            cpa16(&Bs[0][k*136 + c4], B + (size_t)k*ldb + col0 + c4);
        }
        cp_commit();
    }

    for (int it = 0; it < niter; it++) {
        if (it + 1 < niter) {
            int k0 = (it + 1) * 16, nb = (it + 1) & 1;
#pragma unroll
            for (int i = 0; i < 2; i++) {
                int idx = tid + i*256; int m = idx >> 2, c4 = (idx & 3) * 4;
                cpa16(&As[nb][m*20 + c4], A + (size_t)(row0 + m)*lda + k0 + c4);
            }
#pragma unroll
            for (int i = 0; i < 2; i++) {
                int idx = tid + i*256; int k = idx >> 5, c4 = (idx & 31) * 4;
                cpa16(&Bs[nb][k*136 + c4], B + (size_t)(k0 + k)*ldb + col0 + c4);
            }
            cp_commit();
            cp_wait<1>();
        } else {
            cp_wait<0>();
        }
        __syncthreads();
        const uint32_t* Ab = As[it & 1];
        const uint32_t* Bb = Bs[it & 1];
#pragma unroll
        for (int ks = 0; ks < 16; ks += 8) {
            uint32_t af[4][4], bf[4][2];
#pragma unroll
            for (int mi = 0; mi < 4; mi++) {
                int m = wm + mi*16 + (lane >> 2), kk = ks + (lane & 3);
                af[mi][0] = Ab[m*20 + kk];       af[mi][1] = Ab[(m+8)*20 + kk];
                af[mi][2] = Ab[m*20 + kk + 4];   af[mi][3] = Ab[(m+8)*20 + kk + 4];
            }
#pragma unroll
            for (int ni = 0; ni < 4; ni++) {
                int n = wn + ni*8 + (lane >> 2), kb = ks + (lane & 3);
                bf[ni][0] = Bb[kb*136 + n];  bf[ni][1] = Bb[(kb+4)*136 + n];
            }
#pragma unroll
            for (int mi = 0; mi < 4; mi++)
#pragma unroll
                for (int ni = 0; ni < 4; ni++)
                    mma8(acc[mi][ni], af[mi], bf[ni]);
        }
        __syncthreads();
    }

#pragma unroll
    for (int mi = 0; mi < 4; mi++) {
#pragma unroll
        for (int ni = 0; ni < 4; ni++) {
            int r = row0 + wm + mi*16 + (lane >> 2);
            int c = col0 + wn + ni*8 + 2*(lane & 3);
#pragma unroll
            for (int half = 0; half < 2; half++) {
                int rr = r + half*8;
                float v0 = acc[mi][ni][half*2 + 0];
                float v1 = acc[mi][ni][half*2 + 1];
                if (MODE == 1) {
                    v0 += bias[c]   + res[(size_t)rr*ldr + c];
                    v1 += bias[c+1] + res[(size_t)rr*ldr + c + 1];
                } else if (MODE == 2) {
                    v0 = fmaxf(v0 + bias[c], 0.f);
                    v1 = fmaxf(v1 + bias[c+1], 0.f);
                }
                if (ROUND) { v0 = f2tf(v0); v1 = f2tf(v1); }
                *(float2*)(C + (size_t)rr*ldc + c) = make_float2(v0, v1);
            }
        }
    }
}

// ---------------- fused attention v3: 64-row Q tiles, 512 thr, 2 CTAs/SM ---------
// grid (S/64, B*NH). 32 iters of 64 keys, K/V double buffered.
// Inputs Q,K,V are pre-rounded to tf32 grid. E rounded at store. ao rounded.
__global__ void __launch_bounds__(512, 2)
fused_attn(const float* __restrict__ Q, const float* __restrict__ KV,
           float* __restrict__ Eout, float* __restrict__ rs_g,
           float* __restrict__ Og)
{
    extern __shared__ float sm[];
    float* Qs = sm;                    // [64][68]
    float* Ks = Qs + 64*68;            // [2][64][68]
    float* Vs = Ks + 2*64*68;          // [2][64][72]
    float* Es = Vs + 2*64*72;          // [64][68]
    float* rs = Es + 64*68;            // [64]
    const uint32_t* Qsu = (const uint32_t*)Qs;
    const uint32_t* Esu = (const uint32_t*)Es;

    int bh = blockIdx.y, b = bh >> 4, h = bh & 15;
    int n0 = blockIdx.x * 64;
    const float* Qp = Q  + (size_t)b*SS*DD     + h*64;
    const float* Kp = KV + (size_t)b*SS*(2*DD) + h*64;
    const float* Vp = Kp + DD;
    float* Ep = Eout + (size_t)bh*SS*SS + (size_t)n0*SS;

    int tid = threadIdx.x, lane = tid & 31, w = tid >> 5;
    int wy = w & 1, wx = w >> 1;       // wy: 32-row half of 64; wx: 8-col group of 64

    if (tid < 64) rs[tid] = 0.f;

    // Q tile (64x16 float4) + K/V tile 0
#pragma unroll
    for (int i = 0; i < 2; i++) {
        int idx = tid + i*512; int r = idx >> 4, c4 = (idx & 15) * 4;
        cpa16(&Qs[r*68 + c4], Qp + (size_t)(n0 + r)*DD + c4);
        cpa16(&Ks[r*68 + c4], Kp + (size_t)r*(2*DD) + c4);
        cpa16(&Vs[r*72 + c4], Vp + (size_t)r*(2*DD) + c4);
    }
    cp_commit();
    // K/V tile 1
#pragma unroll
    for (int i = 0; i < 2; i++) {
        int idx = tid + i*512; int r = idx >> 4, c4 = (idx & 15) * 4;
        cpa16(&Ks[64*68 + r*68 + c4], Kp + (size_t)(64 + r)*(2*DD) + c4);
        cpa16(&Vs[64*72 + r*72 + c4], Vp + (size_t)(64 + r)*(2*DD) + c4);
    }
    cp_commit();

    float acc_o[2][4];
    float psum[2][2];
#pragma unroll
    for (int i = 0; i < 2; i++) {
        psum[i][0] = psum[i][1] = 0.f;
#pragma unroll
        for (int l = 0; l < 4; l++) acc_o[i][l] = 0.f;
    }

    for (int it = 0; it < 32; it++) {
        int buf = it & 1;
        int m0 = it * 64;
        if (it + 1 < 32) cp_wait<1>(); else cp_wait<0>();
        __syncthreads();
        const uint32_t* Kb = (const uint32_t*)(Ks + buf*64*68);
        const uint32_t* Vb = (const uint32_t*)(Vs + buf*64*72);

        // ---- S = Q K^T : 64(n) x 64(m), k=64; warp tile 32x8 ----
        float acc_s[2][4];
#pragma unroll
        for (int i = 0; i < 2; i++)
#pragma unroll
            for (int l = 0; l < 4; l++) acc_s[i][l] = 0.f;
#pragma unroll
        for (int ks = 0; ks < 64; ks += 8) {
            uint32_t af[2][4], bf[2];
            int kk = ks + (lane & 3);
#pragma unroll
            for (int mi = 0; mi < 2; mi++) {
                int n = wy*32 + mi*16 + (lane >> 2);
                af[mi][0] = Qsu[n*68 + kk];      af[mi][1] = Qsu[(n+8)*68 + kk];
                af[mi][2] = Qsu[n*68 + kk + 4];  af[mi][3] = Qsu[(n+8)*68 + kk + 4];
            }
            {
                int m = wx*8 + (lane >> 2);
                bf[0] = Kb[m*68 + kk];  bf[1] = Kb[m*68 + kk + 4];
            }
            mma8(acc_s[0], af[0], bf);
            mma8(acc_s[1], af[1], bf);
        }

        // ---- E = round(exp(S/8)); per-thread rowsum; store to Es ----
#pragma unroll
        for (int mi = 0; mi < 2; mi++) {
            int r = wy*32 + mi*16 + (lane >> 2);
            int m = wx*8 + 2*(lane & 3);
            float e0 = f2tf(__expf(acc_s[mi][0] * 0.125f));
            float e1 = f2tf(__expf(acc_s[mi][1] * 0.125f));
            float e2 = f2tf(__expf(acc_s[mi][2] * 0.125f));
            float e3 = f2tf(__expf(acc_s[mi][3] * 0.125f));
            *(float2*)&Es[r*68 + m]     = make_float2(e0, e1);
            *(float2*)&Es[(r+8)*68 + m] = make_float2(e2, e3);
            psum[mi][0] += e0 + e1;
            psum[mi][1] += e2 + e3;
        }
        __syncthreads();

        // ---- coalesced E tile write (64 x 64) ----
        {
            int r = tid >> 3, q = (tid & 7) * 2;
            const float4* src = (const float4*)&Es[r*68];
            float4* dst = (float4*)(Ep + (size_t)r*SS + m0);
            dst[q] = src[q]; dst[q + 1] = src[q + 1];
        }

        // ---- O += E V : 64(n) x 64(d), k=64; warp tile 32x8 ----
#pragma unroll
        for (int ks = 0; ks < 64; ks += 8) {
            uint32_t af[2][4], bf[2];
            int kk = ks + (lane & 3);
#pragma unroll
            for (int mi = 0; mi < 2; mi++) {
                int n = wy*32 + mi*16 + (lane >> 2);
                af[mi][0] = Esu[n*68 + kk];      af[mi][1] = Esu[(n+8)*68 + kk];
                af[mi][2] = Esu[n*68 + kk + 4];  af[mi][3] = Esu[(n+8)*68 + kk + 4];
            }
            {
                int d = wx*8 + (lane >> 2);
                bf[0] = Vb[kk*72 + d];  bf[1] = Vb[(kk+4)*72 + d];
            }
            mma8(acc_o[0], af[0], bf);
            mma8(acc_o[1], af[1], bf);
        }
        __syncthreads();

        // ---- prefetch K/V tile it+2 into buf ----
        if (it + 2 < 32) {
            int mn = (it + 2) * 64;
#pragma unroll
            for (int i = 0; i < 2; i++) {
                int idx = tid + i*512; int r = idx >> 4, c4 = (idx & 15) * 4;
                cpa16(&Ks[buf*64*68 + r*68 + c4], Kp + (size_t)(mn + r)*(2*DD) + c4);
                cpa16(&Vs[buf*64*72 + r*72 + c4], Vp + (size_t)(mn + r)*(2*DD) + c4);
            }
            cp_commit();
        }
    }

    // ---- rowsum reduction (once) ----
#pragma unroll
    for (int mi = 0; mi < 2; mi++) {
        int r = wy*32 + mi*16 + (lane >> 2);
        float p0 = psum[mi][0], p1 = psum[mi][1];
        p0 += __shfl_xor_sync(0xffffffffu, p0, 1);
        p0 += __shfl_xor_sync(0xffffffffu, p0, 2);
        p1 += __shfl_xor_sync(0xffffffffu, p1, 1);
        p1 += __shfl_xor_sync(0xffffffffu, p1, 2);
        if ((lane & 3) == 0) { atomicAdd(&rs[r], p0); atomicAdd(&rs[r+8], p1); }
    }
    __syncthreads();

    if (tid < 64) rs_g[(size_t)bh*SS + n0 + tid] = rs[tid];
    float* Op = Og + (size_t)b*SS*DD + h*64;
#pragma unroll
    for (int mi = 0; mi < 2; mi++) {
        int r = wy*32 + mi*16 + (lane >> 2);
        int d = wx*8 + 2*(lane & 3);
        float inv0 = 1.f / rs[r], inv1 = 1.f / rs[r+8];
        *(float2*)(Op + (size_t)(n0 + r)*DD + d) =
            make_float2(f2tf(acc_o[mi][0]*inv0), f2tf(acc_o[mi][1]*inv0));
        *(float2*)(Op + (size_t)(n0 + r + 8)*DD + d) =
            make_float2(f2tf(acc_o[mi][2]*inv1), f2tf(acc_o[mi][3]*inv1));
    }
}

// ---------------- LayerNorm (tf32-rounded output; feeds GEMMs only) --------------
__global__ void __launch_bounds__(256)
ln_kernel(const float* __restrict__ x, const float* __restrict__ g,
          const float* __restrict__ beta, float* __restrict__ out)
{
    __shared__ float red[64];
    int row = blockIdx.x;
    const float* xr = x + (size_t)row*DD;
    float* orow = out + (size_t)row*DD;
    int t = threadIdx.x;
    float v[4]; float s = 0.f, sq = 0.f;
#pragma unroll
    for (int i = 0; i < 4; i++) {
        v[i] = xr[t + i*256];
        s += v[i];
        sq = fmaf(v[i], v[i], sq);
    }
#pragma unroll
    for (int o = 16; o > 0; o >>= 1) {
        s  += __shfl_down_sync(0xffffffffu, s,  o);
        sq += __shfl_down_sync(0xffffffffu, sq, o);
    }
    int lane = t & 31, w = t >> 5;
    if (lane == 0) { red[w] = s; red[w + 32] = sq; }
    __syncthreads();
    if (t == 0) {
        float ts = 0.f, tq = 0.f;
        for (int i = 0; i < 8; i++) { ts += red[i]; tq += red[i + 32]; }
        float mu  = ts * (1.0f / DD);
        float var = tq * (1.0f / DD) - mu * mu;
        red[0] = mu;
        red[1] = rsqrtf(var + 1e-5f);
    }
    __syncthreads();
    float mu = red[0], r = red[1];
#pragma unroll
    for (int i = 0; i < 4; i++) {
        int c = t + i*256;
        orow[c] = f2tf((v[i] - mu) * r * g[c] + beta[c]);
    }
}

// ---------------- Transpose+normalize: E(b,h,n,m)/rowsum -> attn(b,n,m,h) --------
__global__ void __launch_bounds__(256)
attn_transpose(const float* __restrict__ P, const float* __restrict__ rs_g,
               float* __restrict__ outA)
{
    __shared__ float tbuf[16][130];
    __shared__ float invs[16];
    int m0 = blockIdx.x * 128;
    int n  = blockIdx.y;
    int b  = blockIdx.z;
    int t  = threadIdx.x;
    if (t < 16) invs[t] = 1.f / rs_g[((size_t)(b*NHH + t))*SS + n];
#pragma unroll
    for (int i = 0; i < 8; i++) {
        int idx = t + i*256;          // 0..2047
        int h = idx >> 7, m = idx & 127;
        tbuf[h][m] = P[(((size_t)(b*NHH + h))*SS + n)*SS + m0 + m];
    }
    __syncthreads();
    float* op = outA + (((size_t)b*SS + n)*SS + m0) * NHH;
#pragma unroll
    for (int i = 0; i < 8; i++) {
        int idx = t + i*256;          // idx = m*16 + h
        int m = idx >> 4, h = idx & 15;
        op[idx] = tbuf[h][m] * invs[h];
    }
}

// ---------------- launcher -------------------------------------------------------
extern "C" void kernel_launch(void* const* d_in, const int* in_sizes, int n_in,
                              void* d_out, int out_size)
{
    const float* x    = (const float*)d_in[0];
    const float* ln1g = (const float*)d_in[1];
    const float* ln1b = (const float*)d_in[2];
    const float* wq   = (const float*)d_in[3];
    const float* wkv  = (const float*)d_in[4];
    const float* wo   = (const float*)d_in[5];
    const float* bo   = (const float*)d_in[6];
    const float* ln2g = (const float*)d_in[7];
    const float* ln2b = (const float*)d_in[8];
    const float* w1   = (const float*)d_in[9];
    const float* b1   = (const float*)d_in[10];
    const float* w2   = (const float*)d_in[11];
    const float* b2   = (const float*)d_in[12];

    float* out = (float*)d_out;
    size_t attn_elems = (size_t)BB * SS * SS * NHH;
    float* out_attn = out + ((size_t)out_size - attn_elems);

    float *hp, *qp, *kvp, *aop, *ffp, *Pp, *rsp, *wrp;
    cudaGetSymbolAddress((void**)&hp,  g_h);
    cudaGetSymbolAddress((void**)&qp,  g_q);
    cudaGetSymbolAddress((void**)&kvp, g_kv);
    cudaGetSymbolAddress((void**)&aop, g_ao);
    cudaGetSymbolAddress((void**)&ffp, g_ff);
    cudaGetSymbolAddress((void**)&Pp,  g_P);
    cudaGetSymbolAddress((void**)&rsp, g_rs);
    cudaGetSymbolAddress((void**)&wrp, g_wr);
    float* x2p = qp;   // reuse: Q dead after fused_attn
    float* h2p = hp;   // reuse: LN1 out dead after q/kv gemms

    // rounded weight copies
    float* wq_r  = wrp;                 // 1M
    float* wkv_r = wrp + 1024*1024;     // 2M
    float* wo_r  = wrp + 3*1024*1024;   // 1M
    float* w1_r  = wrp + 4*1024*1024;   // 4M
    float* w2_r  = wrp + 8*1024*1024;   // 4M

    static int smem_set = 0;
    int attn_smem = (64*68 + 2*64*68 + 2*64*72 + 64*68 + 64) * 4;   // 106752 B
    if (!smem_set) {
        cudaFuncSetAttribute(fused_attn, cudaFuncAttributeMaxDynamicSharedMemorySize,
                             attn_smem);
        smem_set = 1;
    }

    // 0) round weights to tf32 grid
    round4_kernel<<<(DD*DD/4 + 255)/256, 256>>>(wq, wq_r, DD*DD/4);
    round4_kernel<<<(2*DD*DD/4 + 255)/256, 256>>>(wkv, wkv_r, 2*DD*DD/4);
    round4_kernel<<<(DD*DD/4 + 255)/256, 256>>>(wo, wo_r, DD*DD/4);
    round4_kernel<<<(DD*FFF/4 + 255)/256, 256>>>(w1, w1_r, DD*FFF/4);
    round4_kernel<<<(FFF*DD/4 + 255)/256, 256>>>(w2, w2_r, FFF*DD/4);
    // 1) LN1 (rounded output)
    ln_kernel<<<RR, 256>>>(x, ln1g, ln1b, hp);
    // 2) Q = h @ wq (rounded out)
    mma_gemm<0, true><<<dim3(DD/128, RR/128), 256>>>(hp, DD, wq_r, DD, qp, DD, DD,
                                                     nullptr, nullptr, 0);
    // 3) KV = h @ wkv (rounded out)
    mma_gemm<0, true><<<dim3(2*DD/128, RR/128), 256>>>(hp, DD, wkv_r, 2*DD, kvp, 2*DD, DD,
                                                       nullptr, nullptr, 0);
    // 4) fused attention
    fused_attn<<<dim3(SS/64, BB*NHH), 512, attn_smem>>>(qp, kvp, Pp, rsp, aop);
    // 5) attn output (b,n,m,h), normalized
    attn_transpose<<<dim3(SS/128, SS, BB), 256>>>(Pp, rsp, out_attn);
    // 6) x2 = x + O @ wo + bo  (exact fp32 out)
    mma_gemm<1, false><<<dim3(DD/128, RR/128), 256>>>(aop, DD, wo_r, DD, x2p, DD, DD,
                                                      bo, x, DD);
    // 7) LN2 (rounded output)
    ln_kernel<<<RR, 256>>>(x2p, ln2g, ln2b, h2p);
    // 8) FF1 = relu(h2 @ w1 + b1) (rounded out)
    mma_gemm<2, true><<<dim3(FFF/128, RR/128), 256>>>(h2p, DD, w1_r, FFF, ffp, FFF, DD,
                                                      b1, nullptr, 0);
    // 9) out = x2 + FF1 @ w2 + b2  (exact fp32 out)
    mma_gemm<1, false><<<dim3(DD/128, RR/128), 256>>>(ffp, FFF, w2_r, DD, out, DD, FFF,
                                                      b2, x2p, DD);
}

// round 8
// speedup vs baseline: 2.6218x; 1.0414x over previous
#include <cuda_runtime.h>
#include <math.h>
#include <stdint.h>

#define BB 2
#define SS 2048
#define DD 1024
#define NHH 16
#define HDD 64
#define FFF 4096
#define RR (BB*SS)   // 4096 rows

// ---------------- scratch ---------------------------------------------------------
__device__ float g_h [RR*DD];                       // LN1 out / LN2 out
__device__ float g_q [RR*DD];                       // Q       / x2
__device__ float g_kv[RR*2*DD];                     // K|V
__device__ float g_ao[RR*DD];                       // attn output (b,s,(h,d))
__device__ float g_ff[(size_t)RR*FFF];              // FFN hidden
__device__ float g_P [(size_t)BB*NHH*SS*SS];        // unnormalized exp(scores) (b,h,n,m)
__device__ float g_rs[(size_t)BB*NHH*SS];           // softmax row sums
__device__ float g_wr[12*1024*1024];                // tf32-rounded weights

// ---------------- helpers ---------------------------------------------------------
__device__ __forceinline__ void cpa16(void* dst, const void* src) {
    uint32_t d = (uint32_t)__cvta_generic_to_shared(dst);
    asm volatile("cp.async.ca.shared.global [%0], [%1], 16;" :: "r"(d), "l"(src));
}
__device__ __forceinline__ void cp_commit() { asm volatile("cp.async.commit_group;"); }
template<int N> __device__ __forceinline__ void cp_wait() {
    asm volatile("cp.async.wait_group %0;" :: "n"(N));
}
__device__ __forceinline__ float f2tf(float x) {
    uint32_t r;
    asm("cvt.rna.tf32.f32 %0, %1;" : "=r"(r) : "f"(x));
    return __uint_as_float(r);
}
__device__ __forceinline__ void mma8(float* c, const uint32_t* a, const uint32_t* b) {
    asm volatile(
        "mma.sync.aligned.m16n8k8.row.col.f32.tf32.tf32.f32 "
        "{%0,%1,%2,%3},{%4,%5,%6,%7},{%8,%9},{%0,%1,%2,%3};"
        : "+f"(c[0]), "+f"(c[1]), "+f"(c[2]), "+f"(c[3])
        : "r"(a[0]), "r"(a[1]), "r"(a[2]), "r"(a[3]), "r"(b[0]), "r"(b[1]));
}
// ldmatrix x4: loads a full 16x8 tf32 A-fragment (a0..a3) in one instruction.
__device__ __forceinline__ void ldsm4(uint32_t* r, uint32_t a) {
    asm volatile("ldmatrix.sync.aligned.m8n8.x4.shared.b16 {%0,%1,%2,%3}, [%4];"
        : "=r"(r[0]), "=r"(r[1]), "=r"(r[2]), "=r"(r[3]) : "r"(a));
}

// ---------------- tf32 rounding prep (weights) ------------------------------------
__global__ void __launch_bounds__(256)
round4_kernel(const float* __restrict__ in, float* __restrict__ out, int n4)
{
    int i = blockIdx.x * 256 + threadIdx.x;
    if (i < n4) {
        float4 v = ((const float4*)in)[i];
        v.x = f2tf(v.x); v.y = f2tf(v.y); v.z = f2tf(v.z); v.w = f2tf(v.w);
        ((float4*)out)[i] = v;
    }
}

// ---------------- dense tf32 GEMM v2 ----------------------------------------------
// 128x128 tile, BK=32, 3-stage cp.async pipeline, ONE syncthreads per iter,
// ldmatrix for A fragments. 256 thr (8 warps 2m x 4n), warp tile 64x32.
// Dynamic smem: 3 stages x (A 128x36 + B 32x136) u32 = 107520 B.
// MODE 0: C=acc   1: C=acc+bias+res   2: C=relu(acc+bias)   ROUND: tf32-round out.
#define GSTG 8960              // u32 per stage (4608 A + 4352 B)
#define GSMEM_BYTES (3*GSTG*4)
template<int MODE, bool ROUND>
__global__ void __launch_bounds__(256, 2)
mma_gemm(const float* __restrict__ A, int lda,
         const float* __restrict__ B, int ldb,
         float* __restrict__ C, int ldc, int K,
         const float* __restrict__ bias,
         const float* __restrict__ res, int ldr)
{
    extern __shared__ uint32_t smu[];
    float* smf = (float*)smu;

    int tid = threadIdx.x, lane = tid & 31, w = tid >> 5;
    int wm = (w & 1) * 64, wn = (w >> 1) * 32;
    int row0 = blockIdx.y * 128, col0 = blockIdx.x * 128;

    // ldmatrix per-lane address offsets (bytes) for the 4 A m-tiles
    int i8 = lane & 7, j8 = lane >> 3;
    uint32_t abase = (uint32_t)__cvta_generic_to_shared(smu);
    uint32_t aoff[4];
#pragma unroll
    for (int mi = 0; mi < 4; mi++)
        aoff[mi] = ((wm + mi*16 + i8 + (j8 & 1)*8)*36 + (j8 >> 1)*4) * 4;

    float acc[4][4][4];
#pragma unroll
    for (int i = 0; i < 4; i++)
#pragma unroll
        for (int j = 0; j < 4; j++)
#pragma unroll
            for (int l = 0; l < 4; l++) acc[i][j][l] = 0.f;

    int niter = K / 32;

    // load one 32-k block into stage s
    auto load_blk = [&](int s, int k0) {
        float* As = smf + s*GSTG;
        float* Bs = smf + s*GSTG + 4608;
#pragma unroll
        for (int i = 0; i < 4; i++) {
            int idx = tid + i*256;             // [0,1024)
            int m = idx >> 3, k4 = (idx & 7) * 4;
            cpa16(&As[m*36 + k4], A + (size_t)(row0 + m)*lda + k0 + k4);
        }
#pragma unroll
        for (int i = 0; i < 4; i++) {
            int idx = tid + i*256;
            int k = idx >> 5, c4 = (idx & 31) * 4;
            cpa16(&Bs[k*136 + c4], B + (size_t)(k0 + k)*ldb + col0 + c4);
        }
        cp_commit();
    };

    load_blk(0, 0);
    load_blk(1, 32);

    for (int it = 0; it < niter; it++) {
        cp_wait<1>();
        __syncthreads();
        if (it + 2 < niter) load_blk((it + 2) % 3, (it + 2) * 32);

        int s = it % 3;
        const uint32_t* Bb = smu + s*GSTG + 4608;
        uint32_t as_base = abase + s*GSTG*4;
#pragma unroll
        for (int ks = 0; ks < 32; ks += 8) {
            uint32_t af[4][4], bf[4][2];
#pragma unroll
            for (int mi = 0; mi < 4; mi++)
                ldsm4(af[mi], as_base + aoff[mi] + ks*4);
#pragma unroll
            for (int ni = 0; ni < 4; ni++) {
                int n = wn + ni*8 + (lane >> 2), kb = ks + (lane & 3);
                bf[ni][0] = Bb[kb*136 + n];  bf[ni][1] = Bb[(kb+4)*136 + n];
            }
#pragma unroll
            for (int mi = 0; mi < 4; mi++)
#pragma unroll
                for (int ni = 0; ni < 4; ni++)
                    mma8(acc[mi][ni], af[mi], bf[ni]);
        }
    }

#pragma unroll
    for (int mi = 0; mi < 4; mi++) {
#pragma unroll
        for (int ni = 0; ni < 4; ni++) {
            int r = row0 + wm + mi*16 + (lane >> 2);
            int c = col0 + wn + ni*8 + 2*(lane & 3);
#pragma unroll
            for (int half = 0; half < 2; half++) {
                int rr = r + half*8;
                float v0 = acc[mi][ni][half*2 + 0];
                float v1 = acc[mi][ni][half*2 + 1];
                if (MODE == 1) {
                    v0 += bias[c]   + res[(size_t)rr*ldr + c];
                    v1 += bias[c+1] + res[(size_t)rr*ldr + c + 1];
                } else if (MODE == 2) {
                    v0 = fmaxf(v0 + bias[c], 0.f);
                    v1 = fmaxf(v1 + bias[c+1], 0.f);
                }
                if (ROUND) { v0 = f2tf(v0); v1 = f2tf(v1); }
                *(float2*)(C + (size_t)rr*ldc + c) = make_float2(v0, v1);
            }
        }
    }
}

// ---------------- fused attention v4: ldmatrix fragments --------------------------
// grid (S/64, B*NH), 512 thr, 2 CTAs/SM. 32 iters of 64 keys, K/V double buffered.
__global__ void __launch_bounds__(512, 2)
fused_attn(const float* __restrict__ Q, const float* __restrict__ KV,
           float* __restrict__ Eout, float* __restrict__ rs_g,
           float* __restrict__ Og)
{
    extern __shared__ float sm[];
    float* Qs = sm;                    // [64][68]
    float* Ks = Qs + 64*68;            // [2][64][68]
    float* Vs = Ks + 2*64*68;          // [2][64][72]
    float* Es = Vs + 2*64*72;          // [64][68]
    float* rs = Es + 64*68;            // [64]

    int bh = blockIdx.y, b = bh >> 4, h = bh & 15;
    int n0 = blockIdx.x * 64;
    const float* Qp = Q  + (size_t)b*SS*DD     + h*64;
    const float* Kp = KV + (size_t)b*SS*(2*DD) + h*64;
    const float* Vp = Kp + DD;
    float* Ep = Eout + (size_t)bh*SS*SS + (size_t)n0*SS;

    int tid = threadIdx.x, lane = tid & 31, w = tid >> 5;
    int wy = w & 1, wx = w >> 1;       // wy: 32-row half of 64; wx: 8-col group of 64

    // ldmatrix per-lane offsets for Q / E m-tiles (stride 68)
    int i8 = lane & 7, j8 = lane >> 3;
    uint32_t qbase = (uint32_t)__cvta_generic_to_shared(Qs);
    uint32_t ebase = (uint32_t)__cvta_generic_to_shared(Es);
    uint32_t moff[2];
#pragma unroll
    for (int mi = 0; mi < 2; mi++)
        moff[mi] = ((wy*32 + mi*16 + i8 + (j8 & 1)*8)*68 + (j8 >> 1)*4) * 4;

    if (tid < 64) rs[tid] = 0.f;

#pragma unroll
    for (int i = 0; i < 2; i++) {
        int idx = tid + i*512; int r = idx >> 4, c4 = (idx & 15) * 4;
        cpa16(&Qs[r*68 + c4], Qp + (size_t)(n0 + r)*DD + c4);
        cpa16(&Ks[r*68 + c4], Kp + (size_t)r*(2*DD) + c4);
        cpa16(&Vs[r*72 + c4], Vp + (size_t)r*(2*DD) + c4);
    }
    cp_commit();
#pragma unroll
    for (int i = 0; i < 2; i++) {
        int idx = tid + i*512; int r = idx >> 4, c4 = (idx & 15) * 4;
        cpa16(&Ks[64*68 + r*68 + c4], Kp + (size_t)(64 + r)*(2*DD) + c4);
        cpa16(&Vs[64*72 + r*72 + c4], Vp + (size_t)(64 + r)*(2*DD) + c4);
    }
    cp_commit();

    float acc_o[2][4];
    float psum[2][2];
#pragma unroll
    for (int i = 0; i < 2; i++) {
        psum[i][0] = psum[i][1] = 0.f;
#pragma unroll
        for (int l = 0; l < 4; l++) acc_o[i][l] = 0.f;
    }

    for (int it = 0; it < 32; it++) {
        int buf = it & 1;
        int m0 = it * 64;
        if (it + 1 < 32) cp_wait<1>(); else cp_wait<0>();
        __syncthreads();
        const uint32_t* Kb = (const uint32_t*)(Ks + buf*64*68);
        const uint32_t* Vb = (const uint32_t*)(Vs + buf*64*72);

        // ---- S = Q K^T : 64(n) x 64(m), k=64 ----
        float acc_s[2][4];
#pragma unroll
        for (int i = 0; i < 2; i++)
#pragma unroll
            for (int l = 0; l < 4; l++) acc_s[i][l] = 0.f;
#pragma unroll
        for (int ks = 0; ks < 64; ks += 8) {
            uint32_t af[2][4], bf[2];
            ldsm4(af[0], qbase + moff[0] + ks*4);
            ldsm4(af[1], qbase + moff[1] + ks*4);
            {
                int m = wx*8 + (lane >> 2), kk = ks + (lane & 3);
                bf[0] = Kb[m*68 + kk];  bf[1] = Kb[m*68 + kk + 4];
            }
            mma8(acc_s[0], af[0], bf);
            mma8(acc_s[1], af[1], bf);
        }

        // ---- E = round(exp(S/8)); per-thread rowsum; store to Es ----
#pragma unroll
        for (int mi = 0; mi < 2; mi++) {
            int r = wy*32 + mi*16 + (lane >> 2);
            int m = wx*8 + 2*(lane & 3);
            float e0 = f2tf(__expf(acc_s[mi][0] * 0.125f));
            float e1 = f2tf(__expf(acc_s[mi][1] * 0.125f));
            float e2 = f2tf(__expf(acc_s[mi][2] * 0.125f));
            float e3 = f2tf(__expf(acc_s[mi][3] * 0.125f));
            *(float2*)&Es[r*68 + m]     = make_float2(e0, e1);
            *(float2*)&Es[(r+8)*68 + m] = make_float2(e2, e3);
            psum[mi][0] += e0 + e1;
            psum[mi][1] += e2 + e3;
        }
        __syncthreads();

        // ---- coalesced E tile write (64 x 64) ----
        {
            int r = tid >> 3, q = (tid & 7) * 2;
            const float4* src = (const float4*)&Es[r*68];
            float4* dst = (float4*)(Ep + (size_t)r*SS + m0);
            dst[q] = src[q]; dst[q + 1] = src[q + 1];
        }

        // ---- O += E V : 64(n) x 64(d), k=64 ----
#pragma unroll
        for (int ks = 0; ks < 64; ks += 8) {
            uint32_t af[2][4], bf[2];
            ldsm4(af[0], ebase + moff[0] + ks*4);
            ldsm4(af[1], ebase + moff[1] + ks*4);
            {
                int d = wx*8 + (lane >> 2), kk = ks + (lane & 3);
                bf[0] = Vb[kk*72 + d];  bf[1] = Vb[(kk+4)*72 + d];
            }
            mma8(acc_o[0], af[0], bf);
            mma8(acc_o[1], af[1], bf);
        }
        __syncthreads();

        // ---- prefetch K/V tile it+2 into buf ----
        if (it + 2 < 32) {
            int mn = (it + 2) * 64;
#pragma unroll
            for (int i = 0; i < 2; i++) {
                int idx = tid + i*512; int r = idx >> 4, c4 = (idx & 15) * 4;
                cpa16(&Ks[buf*64*68 + r*68 + c4], Kp + (size_t)(mn + r)*(2*DD) + c4);
                cpa16(&Vs[buf*64*72 + r*72 + c4], Vp + (size_t)(mn + r)*(2*DD) + c4);
            }
            cp_commit();
        }
    }

    // ---- rowsum reduction (once) ----
#pragma unroll
    for (int mi = 0; mi < 2; mi++) {
        int r = wy*32 + mi*16 + (lane >> 2);
        float p0 = psum[mi][0], p1 = psum[mi][1];
        p0 += __shfl_xor_sync(0xffffffffu, p0, 1);
        p0 += __shfl_xor_sync(0xffffffffu, p0, 2);
        p1 += __shfl_xor_sync(0xffffffffu, p1, 1);
        p1 += __shfl_xor_sync(0xffffffffu, p1, 2);
        if ((lane & 3) == 0) { atomicAdd(&rs[r], p0); atomicAdd(&rs[r+8], p1); }
    }
    __syncthreads();

    if (tid < 64) rs_g[(size_t)bh*SS + n0 + tid] = rs[tid];
    float* Op = Og + (size_t)b*SS*DD + h*64;
#pragma unroll
    for (int mi = 0; mi < 2; mi++) {
        int r = wy*32 + mi*16 + (lane >> 2);
        int d = wx*8 + 2*(lane & 3);
        float inv0 = 1.f / rs[r], inv1 = 1.f / rs[r+8];
        *(float2*)(Op + (size_t)(n0 + r)*DD + d) =
            make_float2(f2tf(acc_o[mi][0]*inv0), f2tf(acc_o[mi][1]*inv0));
        *(float2*)(Op + (size_t)(n0 + r + 8)*DD + d) =
            make_float2(f2tf(acc_o[mi][2]*inv1), f2tf(acc_o[mi][3]*inv1));
    }
}

// ---------------- LayerNorm (tf32-rounded output) ---------------------------------
__global__ void __launch_bounds__(256)
ln_kernel(const float* __restrict__ x, const float* __restrict__ g,
          const float* __restrict__ beta, float* __restrict__ out)
{
    __shared__ float red[64];
    int row = blockIdx.x;
    const float* xr = x + (size_t)row*DD;
    float* orow = out + (size_t)row*DD;
    int t = threadIdx.x;
    float v[4]; float s = 0.f, sq = 0.f;
#pragma unroll
    for (int i = 0; i < 4; i++) {
        v[i] = xr[t + i*256];
        s += v[i];
        sq = fmaf(v[i], v[i], sq);
    }
#pragma unroll
    for (int o = 16; o > 0; o >>= 1) {
        s  += __shfl_down_sync(0xffffffffu, s,  o);
        sq += __shfl_down_sync(0xffffffffu, sq, o);
    }
    int lane = t & 31, w = t >> 5;
    if (lane == 0) { red[w] = s; red[w + 32] = sq; }
    __syncthreads();
    if (t == 0) {
        float ts = 0.f, tq = 0.f;
        for (int i = 0; i < 8; i++) { ts += red[i]; tq += red[i + 32]; }
        float mu  = ts * (1.0f / DD);
        float var = tq * (1.0f / DD) - mu * mu;
        red[0] = mu;
        red[1] = rsqrtf(var + 1e-5f);
    }
    __syncthreads();
    float mu = red[0], r = red[1];
#pragma unroll
    for (int i = 0; i < 4; i++) {
        int c = t + i*256;
        orow[c] = f2tf((v[i] - mu) * r * g[c] + beta[c]);
    }
}

// ---------------- Transpose+normalize: E(b,h,n,m)/rowsum -> attn(b,n,m,h) --------
__global__ void __launch_bounds__(256)
attn_transpose(const float* __restrict__ P, const float* __restrict__ rs_g,
               float* __restrict__ outA)
{
    __shared__ float tbuf[16][130];
    __shared__ float invs[16];
    int m0 = blockIdx.x * 128;
    int n  = blockIdx.y;
    int b  = blockIdx.z;
    int t  = threadIdx.x;
    if (t < 16) invs[t] = 1.f / rs_g[((size_t)(b*NHH + t))*SS + n];
#pragma unroll
    for (int i = 0; i < 8; i++) {
        int idx = t + i*256;          // 0..2047
        int h = idx >> 7, m = idx & 127;
        tbuf[h][m] = P[(((size_t)(b*NHH + h))*SS + n)*SS + m0 + m];
    }
    __syncthreads();
    float* op = outA + (((size_t)b*SS + n)*SS + m0) * NHH;
#pragma unroll
    for (int i = 0; i < 8; i++) {
        int idx = t + i*256;          // idx = m*16 + h
        int m = idx >> 4, h = idx & 15;
        op[idx] = tbuf[h][m] * invs[h];
    }
}

// ---------------- launcher -------------------------------------------------------
extern "C" void kernel_launch(void* const* d_in, const int* in_sizes, int n_in,
                              void* d_out, int out_size)
{
    const float* x    = (const float*)d_in[0];
    const float* ln1g = (const float*)d_in[1];
    const float* ln1b = (const float*)d_in[2];
    const float* wq   = (const float*)d_in[3];
    const float* wkv  = (const float*)d_in[4];
    const float* wo   = (const float*)d_in[5];
    const float* bo   = (const float*)d_in[6];
    const float* ln2g = (const float*)d_in[7];
    const float* ln2b = (const float*)d_in[8];
    const float* w1   = (const float*)d_in[9];
    const float* b1   = (const float*)d_in[10];
    const float* w2   = (const float*)d_in[11];
    const float* b2   = (const float*)d_in[12];

    float* out = (float*)d_out;
    size_t attn_elems = (size_t)BB * SS * SS * NHH;
    float* out_attn = out + ((size_t)out_size - attn_elems);

    float *hp, *qp, *kvp, *aop, *ffp, *Pp, *rsp, *wrp;
    cudaGetSymbolAddress((void**)&hp,  g_h);
    cudaGetSymbolAddress((void**)&qp,  g_q);
    cudaGetSymbolAddress((void**)&kvp, g_kv);
    cudaGetSymbolAddress((void**)&aop, g_ao);
    cudaGetSymbolAddress((void**)&ffp, g_ff);
    cudaGetSymbolAddress((void**)&Pp,  g_P);
    cudaGetSymbolAddress((void**)&rsp, g_rs);
    cudaGetSymbolAddress((void**)&wrp, g_wr);
    float* x2p = qp;   // reuse: Q dead after fused_attn
    float* h2p = hp;   // reuse: LN1 out dead after q/kv gemms

    float* wq_r  = wrp;                 // 1M
    float* wkv_r = wrp + 1024*1024;     // 2M
    float* wo_r  = wrp + 3*1024*1024;   // 1M
    float* w1_r  = wrp + 4*1024*1024;   // 4M
    float* w2_r  = wrp + 8*1024*1024;   // 4M

    int attn_smem = (64*68 + 2*64*68 + 2*64*72 + 64*68 + 64) * 4;   // 106752 B
    cudaFuncSetAttribute(fused_attn, cudaFuncAttributeMaxDynamicSharedMemorySize,
                         attn_smem);
    cudaFuncSetAttribute(mma_gemm<0, true>,
                         cudaFuncAttributeMaxDynamicSharedMemorySize, GSMEM_BYTES);
    cudaFuncSetAttribute(mma_gemm<1, false>,
                         cudaFuncAttributeMaxDynamicSharedMemorySize, GSMEM_BYTES);
    cudaFuncSetAttribute(mma_gemm<2, true>,
                         cudaFuncAttributeMaxDynamicSharedMemorySize, GSMEM_BYTES);

    // 0) round weights to tf32 grid
    round4_kernel<<<(DD*DD/4 + 255)/256, 256>>>(wq, wq_r, DD*DD/4);
    round4_kernel<<<(2*DD*DD/4 + 255)/256, 256>>>(wkv, wkv_r, 2*DD*DD/4);
    round4_kernel<<<(DD*DD/4 + 255)/256, 256>>>(wo, wo_r, DD*DD/4);
    round4_kernel<<<(DD*FFF/4 + 255)/256, 256>>>(w1, w1_r, DD*FFF/4);
    round4_kernel<<<(FFF*DD/4 + 255)/256, 256>>>(w2, w2_r, FFF*DD/4);
    // 1) LN1 (rounded output)
    ln_kernel<<<RR, 256>>>(x, ln1g, ln1b, hp);
    // 2) Q = h @ wq (rounded out)
    mma_gemm<0, true><<<dim3(DD/128, RR/128), 256, GSMEM_BYTES>>>(
        hp, DD, wq_r, DD, qp, DD, DD, nullptr, nullptr, 0);
    // 3) KV = h @ wkv (rounded out)
    mma_gemm<0, true><<<dim3(2*DD/128, RR/128), 256, GSMEM_BYTES>>>(
        hp, DD, wkv_r, 2*DD, kvp, 2*DD, DD, nullptr, nullptr, 0);
    // 4) fused attention
    fused_attn<<<dim3(SS/64, BB*NHH), 512, attn_smem>>>(qp, kvp, Pp, rsp, aop);
    // 5) attn output (b,n,m,h), normalized
    attn_transpose<<<dim3(SS/128, SS, BB), 256>>>(Pp, rsp, out_attn);
    // 6) x2 = x + O @ wo + bo
    mma_gemm<1, false><<<dim3(DD/128, RR/128), 256, GSMEM_BYTES>>>(
        aop, DD, wo_r, DD, x2p, DD, DD, bo, x, DD);
    // 7) LN2 (rounded output)
    ln_kernel<<<RR, 256>>>(x2p, ln2g, ln2b, h2p);
    // 8) FF1 = relu(h2 @ w1 + b1) (rounded out)
    mma_gemm<2, true><<<dim3(FFF/128, RR/128), 256, GSMEM_BYTES>>>(
        h2p, DD, w1_r, FFF, ffp, FFF, DD, b1, nullptr, 0);
    // 9) out = x2 + FF1 @ w2 + b2
    mma_gemm<1, false><<<dim3(DD/128, RR/128), 256, GSMEM_BYTES>>>(
        ffp, FFF, w2_r, DD, out, DD, FFF, b2, x2p, DD);
}